// round 13
// baseline (speedup 1.0000x reference)
#include <cuda_runtime.h>
#include <cuda_bf16.h>
#include <math.h>

#define B_   16
#define T_   8192
#define V_   256
#define CE_  256
#define CR_  128
#define CS_  256
#define GC_  64
#define L_   12

#define NT   512
#define XS   132     // x/g tile row stride (floats)

typedef unsigned long long u64;

__device__ float g_xbuf[2][(size_t)B_ * CR_ * T_];   // ping-pong activations
__device__ float g_skip[(size_t)B_ * CS_ * T_];      // skip accumulator

__device__ __forceinline__ u64 pk2(float lo, float hi) {
    u64 r; asm("mov.b64 %0, {%1,%2};" : "=l"(r) : "f"(lo), "f"(hi)); return r;
}
__device__ __forceinline__ u64 bc2(float x) { return pk2(x, x); }
__device__ __forceinline__ void fma2(u64& d, u64 a, u64 b) {
    asm("fma.rn.f32x2 %0, %1, %2, %0;" : "+l"(d) : "l"(a), "l"(b));
}
__device__ __forceinline__ u64 add2(u64 a, u64 b) {
    u64 r; asm("add.rn.f32x2 %0, %1, %2;" : "=l"(r) : "l"(a), "l"(b)); return r;
}
__device__ __forceinline__ float2 up2(u64 a) {
    float2 f; asm("mov.b64 {%0,%1}, %2;" : "=f"(f.x), "=f"(f.y) : "l"(a)); return f;
}
__device__ __forceinline__ float sigmoidf_(float x) {
    return __fdividef(1.0f, 1.0f + __expf(-x));
}

// ============================ init kernel ============================
// x0[b][co][t] = b_init[co] + sum_ce (w0[co][ce] h[t-1] + w1[co][ce] h[t])
__global__ void __launch_bounds__(NT, 1) wn_init(
    const int* __restrict__ tokens, const float* __restrict__ emb,
    const float* __restrict__ w_init, const float* __restrict__ b_init)
{
    __shared__ float hbuf[16 * XS];
    __shared__ float wst[4160];
    __shared__ int   tokb[132];

    const int tid = threadIdx.x;
    const int t0  = blockIdx.x * 128;
    const int bb  = blockIdx.y;

    for (int q = tid; q < 130; q += NT) {
        int t = t0 - 1 + q;
        tokb[q] = (t >= 0 && t < T_) ? tokens[bb * T_ + t] : -1;
    }

    const int cg = tid >> 4, pg = tid & 15;
    const int c0 = 2 * cg, q0 = 2 * pg;

    u64 acc[4][4];
    #pragma unroll
    for (int ic = 0; ic < 4; ++ic)
        #pragma unroll
        for (int k = 0; k < 4; ++k) acc[ic][k] = 0ULL;

    __syncthreads();
    for (int ch = 0; ch < 16; ++ch) {
        const int ceb = ch * 16;
        for (int idx = tid; idx < 130 * 4; idx += NT) {
            int q = idx >> 2; int ce4 = (idx & 3) << 2;
            int tok = tokb[q];
            float4 v = make_float4(0.f, 0.f, 0.f, 0.f);
            if (tok >= 0) v = *reinterpret_cast<const float4*>(emb + tok * CE_ + ceb + ce4);
            hbuf[(ce4 + 0) * XS + q] = v.x;
            hbuf[(ce4 + 1) * XS + q] = v.y;
            hbuf[(ce4 + 2) * XS + q] = v.z;
            hbuf[(ce4 + 3) * XS + q] = v.w;
        }
        for (int idx = tid; idx < 2048; idx += NT) {
            int ce = idx & 15; int co = idx >> 4;
            float2 w2 = *reinterpret_cast<const float2*>(w_init + ((co * CE_ + ceb + ce) << 1));
            wst[ce * 260 + co]       = w2.x;
            wst[ce * 260 + 128 + co] = w2.y;
        }
        __syncthreads();
        #pragma unroll
        for (int ce = 0; ce < 16; ++ce) {
            const float* hr = hbuf + ce * XS;
            const float* wr = wst + ce * 260;
            u64 w00 = bc2(wr[c0]),      w10 = bc2(wr[128 + c0]);
            u64 w01 = bc2(wr[c0 + 1]),  w11 = bc2(wr[128 + c0 + 1]);
            u64 w02 = bc2(wr[c0 + 64]), w12 = bc2(wr[128 + c0 + 64]);
            u64 w03 = bc2(wr[c0 + 65]), w13 = bc2(wr[128 + c0 + 65]);
            #pragma unroll
            for (int k = 0; k < 4; ++k) {
                int q = q0 + 32 * k;
                u64 A = *reinterpret_cast<const u64*>(hr + q);   // h[p-1],h[p]
                float s = hr[q + 2];
                float2 av = up2(A);
                u64 T1 = pk2(av.y, s);                            // h[p],h[p+1]
                fma2(acc[0][k], w00, A); fma2(acc[0][k], w10, T1);
                fma2(acc[1][k], w01, A); fma2(acc[1][k], w11, T1);
                fma2(acc[2][k], w02, A); fma2(acc[2][k], w12, T1);
                fma2(acc[3][k], w03, A); fma2(acc[3][k], w13, T1);
            }
        }
        __syncthreads();
    }
    float* xout = g_xbuf[0] + ((size_t)(bb * CR_)) * T_;
    #pragma unroll
    for (int ic = 0; ic < 4; ++ic) {
        int co = (ic < 2) ? (c0 + ic) : (c0 + 62 + ic);
        u64 bp = bc2(__ldg(b_init + co));
        #pragma unroll
        for (int k = 0; k < 4; ++k) {
            int p = q0 + 32 * k;
            *reinterpret_cast<u64*>(xout + (size_t)co * T_ + t0 + p) = add2(acc[ic][k], bp);
        }
    }
}

// ============================ layer kernel ============================
// smem: xs[128][XS] | gbuf[64][XS] (conv-weight overlay) | wst[4224]
#define LAY_XS   0
#define LAY_GB   (128 * XS)
#define LAY_WST  (LAY_GB + 64 * XS)
#define LAY_SMEM ((LAY_WST + 4224) * 4)

__global__ void __launch_bounds__(NT, 1) wn_layer(
    int l,
    const float* __restrict__ wd,  const float* __restrict__ bd,
    const float* __restrict__ wrp, const float* __restrict__ br,
    const float* __restrict__ wsk, const float* __restrict__ bsk)
{
    extern __shared__ float sm[];
    float* xs   = sm + LAY_XS;
    float* gbuf = sm + LAY_GB;
    float* wst  = sm + LAY_WST;
    float* wstD = gbuf;   // conv weight staging overlays gbuf

    const int tid = threadIdx.x;
    const int t0  = blockIdx.x * 128;
    const int bb  = blockIdx.y;
    const bool first = (l == 0);

    const float* xin = g_xbuf[l & 1]     + ((size_t)(bb * CR_)) * T_;
    float*       xo  = g_xbuf[(l + 1) & 1] + ((size_t)(bb * CR_)) * T_;

    // load x tile: xs[ch][q], q in [0,130): value x[t0-2+q] (zero-padded)
    for (int idx = tid; idx < 128 * 65; idx += NT) {
        int ch = idx / 65; int qq = idx - ch * 65;
        int t = t0 - 2 + 2 * qq;
        float2 v = make_float2(0.f, 0.f);
        if (t >= 0) v = *reinterpret_cast<const float2*>(xin + (size_t)ch * T_ + t);
        *reinterpret_cast<float2*>(xs + ch * XS + 2 * qq) = v;
    }

    const int cg = tid >> 4, pg = tid & 15;
    const int c0 = 2 * cg, q0 = 2 * pg;

    // ---- dilated conv (k=2, d=2): out p uses xs[p] and xs[p+2] ----
    u64 acc2[4][4];
    #pragma unroll
    for (int ic = 0; ic < 4; ++ic)
        #pragma unroll
        for (int k = 0; k < 4; ++k) acc2[ic][k] = 0ULL;

    for (int ch4 = 0; ch4 < 4; ++ch4) {
        const int cib = ch4 * 32;
        __syncthreads();   // first iter: covers xs load; later: wstD readers done
        for (int idx = tid; idx < 4096; idx += NT) {
            int ci = idx & 31; int co = idx >> 5;
            float2 w2 = *reinterpret_cast<const float2*>(wd + ((co * CR_ + cib + ci) << 1));
            *reinterpret_cast<u64*>(wstD + ci * 260 + 2 * co) = pk2(w2.x, w2.y);
        }
        __syncthreads();
        #pragma unroll
        for (int ci = 0; ci < 32; ++ci) {
            const float* xr = xs + (cib + ci) * XS;
            u64 a0[4], a1[4];
            #pragma unroll
            for (int k = 0; k < 4; ++k) {
                int p = q0 + 32 * k;
                a0[k] = *reinterpret_cast<const u64*>(xr + p);
                a1[k] = *reinterpret_cast<const u64*>(xr + p + 2);
            }
            const float* wr = wstD + ci * 260 + 2 * c0;
            float4 wlo = *reinterpret_cast<const float4*>(wr);
            float4 whi = *reinterpret_cast<const float4*>(wr + 128);
            u64 b0 = bc2(wlo.x), b1 = bc2(wlo.y), b2 = bc2(wlo.z), b3 = bc2(wlo.w);
            u64 b4 = bc2(whi.x), b5 = bc2(whi.y), b6 = bc2(whi.z), b7 = bc2(whi.w);
            #pragma unroll
            for (int k = 0; k < 4; ++k) {
                fma2(acc2[0][k], b0, a0[k]); fma2(acc2[0][k], b1, a1[k]);
                fma2(acc2[1][k], b2, a0[k]); fma2(acc2[1][k], b3, a1[k]);
                fma2(acc2[2][k], b4, a0[k]); fma2(acc2[2][k], b5, a1[k]);
                fma2(acc2[3][k], b6, a0[k]); fma2(acc2[3][k], b7, a1[k]);
            }
        }
    }
    __syncthreads();   // conv reads of wstD(gbuf) done before gate writes gbuf

    // ---- gate ----
    {
        float gb0 = __ldg(bd + c0), gb1 = __ldg(bd + c0 + 1);
        float gb2 = __ldg(bd + c0 + 64), gb3 = __ldg(bd + c0 + 65);
        #pragma unroll
        for (int k = 0; k < 4; ++k) {
            int p = q0 + 32 * k;
            float2 a0 = up2(acc2[0][k]);
            float2 a1 = up2(acc2[1][k]);
            float2 h0 = up2(acc2[2][k]);
            float2 h1 = up2(acc2[3][k]);
            float g0a = tanhf(a0.x + gb0) * sigmoidf_(h0.x + gb2);
            float g0b = tanhf(a0.y + gb0) * sigmoidf_(h0.y + gb2);
            float g1a = tanhf(a1.x + gb1) * sigmoidf_(h1.x + gb3);
            float g1b = tanhf(a1.y + gb1) * sigmoidf_(h1.y + gb3);
            *reinterpret_cast<u64*>(gbuf + c0 * XS + p)       = pk2(g0a, g0b);
            *reinterpret_cast<u64*>(gbuf + (c0 + 1) * XS + p) = pk2(g1a, g1b);
        }
    }
    __syncthreads();

    // ---- skip: 2 cs channels x 16 pairs, RMW to gmem ----
    {
        const int cs0 = 2 * (tid >> 2);
        const int j0  = 32 * (tid & 3);
        u64 s0[16], s1[16];
        #pragma unroll
        for (int kk = 0; kk < 16; ++kk) { s0[kk] = 0ULL; s1[kk] = 0ULL; }
        for (int gch = 0; gch < 4; ++gch) {
            const int gcb = gch * 16;
            for (int idx = tid; idx < 4096; idx += NT) {
                int gc = idx & 15; int cs = idx >> 4;
                wst[gc * 260 + cs] = wsk[cs * GC_ + gcb + gc];
            }
            __syncthreads();
            #pragma unroll
            for (int gc = 0; gc < 16; ++gc) {
                const float* wrow = wst + gc * 260;
                u64 wb0 = bc2(wrow[cs0]);
                u64 wb1 = bc2(wrow[cs0 + 1]);
                const u64* gr = reinterpret_cast<const u64*>(gbuf + (gcb + gc) * XS + j0);
                #pragma unroll
                for (int kk = 0; kk < 16; ++kk) {
                    u64 gv = gr[kk];
                    fma2(s0[kk], wb0, gv);
                    fma2(s1[kk], wb1, gv);
                }
            }
            __syncthreads();
        }
        u64 bb0 = bc2(__ldg(bsk + cs0));
        u64 bb1 = bc2(__ldg(bsk + cs0 + 1));
        u64* sp0 = reinterpret_cast<u64*>(g_skip + ((size_t)(bb * CS_ + cs0)) * T_ + t0 + j0);
        u64* sp1 = reinterpret_cast<u64*>(g_skip + ((size_t)(bb * CS_ + cs0 + 1)) * T_ + t0 + j0);
        if (first) {
            #pragma unroll
            for (int kk = 0; kk < 16; ++kk) {
                sp0[kk] = add2(s0[kk], bb0);
                sp1[kk] = add2(s1[kk], bb1);
            }
        } else {
            #pragma unroll
            for (int kk = 0; kk < 16; ++kk) {
                sp0[kk] = add2(sp0[kk], add2(s0[kk], bb0));
                sp1[kk] = add2(sp1[kk], add2(s1[kk], bb1));
            }
        }
    }

    // ---- residual: x_out = x_in + W_res g (+b) ----
    {
        u64 racc[4][4];
        #pragma unroll
        for (int ic = 0; ic < 4; ++ic)
            #pragma unroll
            for (int k = 0; k < 4; ++k) racc[ic][k] = 0ULL;
        for (int gch = 0; gch < 2; ++gch) {
            const int gcb = gch * 32;
            __syncthreads();   // skip compute done with wst
            for (int idx = tid; idx < 4096; idx += NT) {
                int gc = idx & 31; int co = idx >> 5;
                wst[gc * 130 + co] = wrp[co * GC_ + gcb + gc];
            }
            __syncthreads();
            #pragma unroll
            for (int gc = 0; gc < 32; ++gc) {
                const float* grow = gbuf + (gcb + gc) * XS;
                u64 g0 = *reinterpret_cast<const u64*>(grow + q0);
                u64 g1 = *reinterpret_cast<const u64*>(grow + q0 + 32);
                u64 g2 = *reinterpret_cast<const u64*>(grow + q0 + 64);
                u64 g3 = *reinterpret_cast<const u64*>(grow + q0 + 96);
                const float* wrow = wst + gc * 130;
                float2 wlo = *reinterpret_cast<const float2*>(wrow + c0);
                float2 whi = *reinterpret_cast<const float2*>(wrow + c0 + 64);
                u64 w0 = bc2(wlo.x), w1 = bc2(wlo.y), w2 = bc2(whi.x), w3 = bc2(whi.y);
                fma2(racc[0][0], w0, g0); fma2(racc[0][1], w0, g1);
                fma2(racc[0][2], w0, g2); fma2(racc[0][3], w0, g3);
                fma2(racc[1][0], w1, g0); fma2(racc[1][1], w1, g1);
                fma2(racc[1][2], w1, g2); fma2(racc[1][3], w1, g3);
                fma2(racc[2][0], w2, g0); fma2(racc[2][1], w2, g1);
                fma2(racc[2][2], w2, g2); fma2(racc[2][3], w2, g3);
                fma2(racc[3][0], w3, g0); fma2(racc[3][1], w3, g1);
                fma2(racc[3][2], w3, g2); fma2(racc[3][3], w3, g3);
            }
        }
        #pragma unroll
        for (int ic = 0; ic < 4; ++ic) {
            int co = (ic < 2) ? (c0 + ic) : (c0 + 62 + ic);
            u64 bp = bc2(__ldg(br + co));
            #pragma unroll
            for (int k = 0; k < 4; ++k) {
                int p = q0 + 32 * k;
                u64 xv = *reinterpret_cast<const u64*>(xs + co * XS + p + 2);  // x[t]
                *reinterpret_cast<u64*>(xo + (size_t)co * T_ + t0 + p) =
                    add2(xv, add2(racc[ic][k], bp));
            }
        }
    }
}

// ============================ head kernel ============================
// TP=64: s tile [256][66], o1 [256][66], wst[4160]
#define HD_S    0
#define HD_O1   (256 * 66)
#define HD_WST  (HD_O1 + 256 * 66)
#define HD_SMEM ((HD_WST + 4160) * 4)

__global__ void __launch_bounds__(NT, 1) wn_head(
    const float* __restrict__ w_out1, const float* __restrict__ b_out1,
    const float* __restrict__ w_out2, const float* __restrict__ b_out2,
    float* __restrict__ out)
{
    extern __shared__ float sm[];
    float* sbuf  = sm + HD_S;
    float* o1buf = sm + HD_O1;
    float* wst   = sm + HD_WST;

    const int tid = threadIdx.x;
    const int t0  = blockIdx.x * 64;
    const int bb  = blockIdx.y;

    // load s = relu(skip/12)
    for (int idx = tid; idx < 256 * 32; idx += NT) {
        int c = idx >> 5; int qq = idx & 31;
        float2 v = *reinterpret_cast<const float2*>(
            g_skip + ((size_t)(bb * CS_ + c)) * T_ + t0 + 2 * qq);
        v.x *= (1.0f / 12.0f); v.x = v.x > 0.f ? v.x : 0.f;
        v.y *= (1.0f / 12.0f); v.y = v.y > 0.f ? v.y : 0.f;
        *reinterpret_cast<float2*>(sbuf + c * 66 + 2 * qq) = v;
    }

    const int c0h = tid >> 1;
    const int jh  = 32 * (tid & 1);

    // ---- out1 ----
    u64 a2p[16];
    #pragma unroll
    for (int kk = 0; kk < 16; ++kk) a2p[kk] = 0ULL;
    for (int kch = 0; kch < 16; ++kch) {
        const int kb = kch * 16;
        __syncthreads();   // first iter covers sbuf load
        for (int idx = tid; idx < 4096; idx += NT) {
            int k = idx & 15; int c = idx >> 4;
            wst[k * 260 + c] = w_out1[c * CS_ + kb + k];
        }
        __syncthreads();
        #pragma unroll 4
        for (int k = 0; k < 16; ++k) {
            u64 wb = bc2(wst[k * 260 + c0h]);
            const u64* sr = reinterpret_cast<const u64*>(sbuf + (kb + k) * 66 + jh);
            #pragma unroll
            for (int kk = 0; kk < 16; ++kk) fma2(a2p[kk], wb, sr[kk]);
        }
    }
    __syncthreads();
    {
        float bi = __ldg(b_out1 + c0h);
        float* op = o1buf + c0h * 66 + jh;
        #pragma unroll
        for (int kk = 0; kk < 16; ++kk) {
            float2 v = up2(a2p[kk]);
            float v0 = v.x + bi; v0 = v0 > 0.f ? v0 : 0.f;
            float v1 = v.y + bi; v1 = v1 > 0.f ? v1 : 0.f;
            *reinterpret_cast<u64*>(op + 2 * kk) = pk2(v0, v1);
        }
    }
    // ---- out2 ----
    u64 a3p[16];
    #pragma unroll
    for (int kk = 0; kk < 16; ++kk) a3p[kk] = 0ULL;
    for (int kch = 0; kch < 16; ++kch) {
        const int kb = kch * 16;
        __syncthreads();   // first iter covers o1 writes
        for (int idx = tid; idx < 4096; idx += NT) {
            int k = idx & 15; int c = idx >> 4;
            wst[k * 260 + c] = w_out2[c * CS_ + kb + k];
        }
        __syncthreads();
        #pragma unroll 4
        for (int k = 0; k < 16; ++k) {
            u64 wb = bc2(wst[k * 260 + c0h]);
            const u64* orr = reinterpret_cast<const u64*>(o1buf + (kb + k) * 66 + jh);
            #pragma unroll
            for (int kk = 0; kk < 16; ++kk) fma2(a3p[kk], wb, orr[kk]);
        }
    }
    {
        float bo = __ldg(b_out2 + c0h);
        float* orow = out + ((size_t)(bb * V_ + c0h)) * T_ + t0 + jh;
        #pragma unroll
        for (int kk = 0; kk < 16; ++kk) {
            float2 v = up2(a3p[kk]);
            v.x += bo; v.y += bo;
            *reinterpret_cast<float2*>(orow + 2 * kk) = v;
        }
    }
}

extern "C" void kernel_launch(void* const* d_in, const int* in_sizes, int n_in,
                              void* d_out, int out_size) {
    const int*   tokens = (const int*)  d_in[0];
    const float* emb    = (const float*)d_in[1];
    const float* w_init = (const float*)d_in[2];
    const float* b_init = (const float*)d_in[3];
    const float* w_dil  = (const float*)d_in[4];
    const float* b_dil  = (const float*)d_in[5];
    const float* w_res  = (const float*)d_in[6];
    const float* b_res  = (const float*)d_in[7];
    const float* w_skip = (const float*)d_in[8];
    const float* b_skip = (const float*)d_in[9];
    const float* w_out1 = (const float*)d_in[10];
    const float* b_out1 = (const float*)d_in[11];
    const float* w_out2 = (const float*)d_in[12];
    const float* b_out2 = (const float*)d_in[13];
    float* out = (float*)d_out;

    cudaFuncSetAttribute(wn_layer, cudaFuncAttributeMaxDynamicSharedMemorySize, LAY_SMEM);
    cudaFuncSetAttribute(wn_head,  cudaFuncAttributeMaxDynamicSharedMemorySize, HD_SMEM);

    dim3 g1(T_ / 128, B_);
    wn_init<<<g1, NT>>>(tokens, emb, w_init, b_init);
    for (int l = 0; l < L_; ++l) {
        wn_layer<<<g1, NT, LAY_SMEM>>>(
            l,
            w_dil  + (size_t)l * CR_ * CR_ * 2, b_dil  + l * CR_,
            w_res  + (size_t)l * CR_ * GC_,     b_res  + l * CR_,
            w_skip + (size_t)l * CS_ * GC_,     b_skip + l * CS_);
    }
    dim3 g2(T_ / 64, B_);
    wn_head<<<g2, NT, HD_SMEM>>>(w_out1, b_out1, w_out2, b_out2, out);
}

// round 14
// speedup vs baseline: 1.7798x; 1.7798x over previous
#include <cuda_runtime.h>
#include <cuda_bf16.h>
#include <math.h>

// Problem constants
#define B_   16
#define T_   8192
#define V_   256
#define CE_  256
#define CR_  128
#define CS_  256
#define GC_  64
#define L_   12

// Tiling
#define TT   104
#define WP   128
#define XS   132
#define SKS  106
#define NT   512
#define O1S  56

// smem layout (floats)
#define OFF_BUFA 0
#define N_BUFA   (128*XS)
#define OFF_GBUF (OFF_BUFA + N_BUFA)
#define N_GBUF   (64*XS)              // 8448; conv-weight staging overlay (32*260=8320)
#define OFF_SKIP (OFF_GBUF + N_GBUF)
#define N_SKIP   (CS_*SKS)
#define OFF_WST  (OFF_SKIP + N_SKIP)
#define N_WST    4224
#define OFF_TOK  (OFF_WST + N_WST)
#define SMEM_BYTES ((OFF_TOK)*4 + 132*4)

typedef unsigned long long u64;

__device__ __forceinline__ u64 pk2(float lo, float hi) {
    u64 r; asm("mov.b64 %0, {%1,%2};" : "=l"(r) : "f"(lo), "f"(hi)); return r;
}
__device__ __forceinline__ u64 bc2(float x) { return pk2(x, x); }
__device__ __forceinline__ void fma2(u64& d, u64 a, u64 b) {
    asm("fma.rn.f32x2 %0, %1, %2, %0;" : "+l"(d) : "l"(a), "l"(b));
}
__device__ __forceinline__ u64 add2(u64 a, u64 b) {
    u64 r; asm("add.rn.f32x2 %0, %1, %2;" : "=l"(r) : "l"(a), "l"(b)); return r;
}
__device__ __forceinline__ float2 up2(u64 a) {
    float2 f; asm("mov.b64 {%0,%1}, %2;" : "=f"(f.x), "=f"(f.y) : "l"(a)); return f;
}
__device__ __forceinline__ float sigmoidf_(float x) {
    return __fdividef(1.0f, 1.0f + __expf(-x));
}

__global__ void __launch_bounds__(NT, 1) wavenet_fused(
    const int*   __restrict__ tokens,
    const float* __restrict__ emb,
    const float* __restrict__ w_init, const float* __restrict__ b_init,
    const float* __restrict__ w_dil,  const float* __restrict__ b_dil,
    const float* __restrict__ w_res,  const float* __restrict__ b_res,
    const float* __restrict__ w_skip, const float* __restrict__ b_skip,
    const float* __restrict__ w_out1, const float* __restrict__ b_out1,
    const float* __restrict__ w_out2, const float* __restrict__ b_out2,
    float* __restrict__ out)
{
    extern __shared__ float sm[];
    float* bufA  = sm + OFF_BUFA;   // x activations [128][XS]
    float* gbuf  = sm + OFF_GBUF;   // gate output [64][XS]; conv-weight staging overlay
    float* skipS = sm + OFF_SKIP;   // skip accum [256][SKS]
    float* wst   = sm + OFF_WST;    // small weight staging
    int*   tokb  = (int*)(sm + OFF_TOK);

    const int tid  = threadIdx.x;
    const int tile = blockIdx.x;
    const int bb   = blockIdx.y;
    const int t0   = tile * TT;
    const int pzero = (tile == 0) ? 24 : 0;

    for (int q = tid; q < WP + 1; q += NT) {
        int t = t0 - 25 + q;
        tokb[q] = (t >= 0 && t < T_) ? tokens[bb * T_ + t] : -1;
    }
    for (int i = tid; i < N_SKIP; i += NT) skipS[i] = 0.0f;

    // conv/residual mapping (proven): 4 channels x 4 strided pairs per thread
    const int cg = tid >> 4;      // 0..31
    const int pg = tid & 15;      // 0..15
    const int c0 = 2 * cg;        // channels {c0, c0+1, c0+64, c0+65}
    const int q0 = 2 * pg;        // pairs at q0 + 32k, k=0..3

    // ======================= init conv (emb -> x0) =======================
    {
        u64 acc[4][4];
        #pragma unroll
        for (int ic = 0; ic < 4; ++ic)
            #pragma unroll
            for (int k = 0; k < 4; ++k) acc[ic][k] = 0ULL;

        __syncthreads();
        for (int ch = 0; ch < 16; ++ch) {       // ce chunks of 16
            const int ceb = ch * 16;
            for (int idx = tid; idx < (WP + 1) * 4; idx += NT) {
                int q = idx >> 2; int ce4 = (idx & 3) << 2;
                int tok = tokb[q];
                float4 v = make_float4(0.f, 0.f, 0.f, 0.f);
                if (tok >= 0) v = *reinterpret_cast<const float4*>(emb + tok * CE_ + ceb + ce4);
                gbuf[(ce4 + 0) * XS + q] = v.x;
                gbuf[(ce4 + 1) * XS + q] = v.y;
                gbuf[(ce4 + 2) * XS + q] = v.z;
                gbuf[(ce4 + 3) * XS + q] = v.w;
            }
            // tap-split staging: wst[ce*260 + tap*128 + co]
            for (int idx = tid; idx < 2048; idx += NT) {
                int ce = idx & 15; int co = idx >> 4;
                float2 w2 = *reinterpret_cast<const float2*>(w_init + ((co * CE_ + ceb + ce) << 1));
                wst[ce * 260 + co]       = w2.x;
                wst[ce * 260 + 128 + co] = w2.y;
            }
            __syncthreads();
            #pragma unroll
            for (int ce = 0; ce < 16; ++ce) {
                const float* hr = gbuf + ce * XS;
                const float* wr = wst + ce * 260;
                u64 w00 = bc2(wr[c0]),        w10 = bc2(wr[128 + c0]);
                u64 w01 = bc2(wr[c0 + 1]),    w11 = bc2(wr[128 + c0 + 1]);
                u64 w02 = bc2(wr[c0 + 64]),   w12 = bc2(wr[128 + c0 + 64]);
                u64 w03 = bc2(wr[c0 + 65]),   w13 = bc2(wr[128 + c0 + 65]);
                #pragma unroll
                for (int k = 0; k < 4; ++k) {
                    int q = q0 + 32 * k;
                    u64 A = *reinterpret_cast<const u64*>(hr + q);
                    float s = hr[q + 2];
                    float2 av = up2(A);
                    u64 T1 = pk2(av.y, s);
                    fma2(acc[0][k], w00, A); fma2(acc[0][k], w10, T1);
                    fma2(acc[1][k], w01, A); fma2(acc[1][k], w11, T1);
                    fma2(acc[2][k], w02, A); fma2(acc[2][k], w12, T1);
                    fma2(acc[3][k], w03, A); fma2(acc[3][k], w13, T1);
                }
            }
            __syncthreads();
        }
        #pragma unroll
        for (int ic = 0; ic < 4; ++ic) {
            int co = (ic < 2) ? (c0 + ic) : (c0 + 62 + ic);
            u64 bp = bc2(__ldg(b_init + co));
            #pragma unroll
            for (int k = 0; k < 4; ++k) {
                int q = q0 + 32 * k;
                u64 v = (q < pzero) ? 0ULL : add2(acc[ic][k], bp);
                *reinterpret_cast<u64*>(bufA + co * XS + q) = v;
            }
        }
    }
    __syncthreads();

    // skip mapping (proven): 2 cs channels x 13 pairs
    const int cs0 = 2 * (tid >> 2);
    const int j0  = 26 * (tid & 3);

    float* wstD = gbuf;   // dilated conv weight staging overlays gbuf

    // ============================ layers ============================
    for (int l = 0; l < L_; ++l) {
        // ---- dilated conv (k=2, d=2) ----
        u64 acc2[4][4];
        #pragma unroll
        for (int ic = 0; ic < 4; ++ic)
            #pragma unroll
            for (int k = 0; k < 4; ++k) acc2[ic][k] = 0ULL;

        const float* wd = w_dil + (size_t)l * CR_ * CR_ * 2;
        for (int ch = 0; ch < 4; ++ch) {        // ci chunks of 32
            const int cib = ch * 32;
            __syncthreads();   // gbuf free (prev consumers done)
            for (int idx = tid; idx < 4096; idx += NT) {
                int ci = idx & 31; int co = idx >> 5;
                float2 w2 = *reinterpret_cast<const float2*>(wd + ((co * CR_ + cib + ci) << 1));
                *reinterpret_cast<u64*>(wstD + ci * 260 + 2 * co) = pk2(w2.x, w2.y);
            }
            __syncthreads();
            #pragma unroll
            for (int ci = 0; ci < 32; ++ci) {
                const float* xr = bufA + (cib + ci) * XS;
                u64 xm[4], xp[4];
                xm[0] = (q0 >= 2) ? *reinterpret_cast<const u64*>(xr + q0 - 2) : 0ULL;
                xp[0] = *reinterpret_cast<const u64*>(xr + q0);
                #pragma unroll
                for (int k = 1; k < 4; ++k) {
                    xm[k] = *reinterpret_cast<const u64*>(xr + q0 + 32 * k - 2);
                    xp[k] = *reinterpret_cast<const u64*>(xr + q0 + 32 * k);
                }
                const float* wr = wstD + ci * 260 + 2 * c0;
                float4 wlo = *reinterpret_cast<const float4*>(wr);
                float4 whi = *reinterpret_cast<const float4*>(wr + 128);
                u64 b0 = bc2(wlo.x), b1 = bc2(wlo.y), b2 = bc2(wlo.z), b3 = bc2(wlo.w);
                u64 b4 = bc2(whi.x), b5 = bc2(whi.y), b6 = bc2(whi.z), b7 = bc2(whi.w);
                #pragma unroll
                for (int k = 0; k < 4; ++k) {
                    fma2(acc2[0][k], b0, xm[k]); fma2(acc2[0][k], b1, xp[k]);
                    fma2(acc2[1][k], b2, xm[k]); fma2(acc2[1][k], b3, xp[k]);
                    fma2(acc2[2][k], b4, xm[k]); fma2(acc2[2][k], b5, xp[k]);
                    fma2(acc2[3][k], b6, xm[k]); fma2(acc2[3][k], b7, xp[k]);
                }
            }
        }
        __syncthreads();   // conv reads of wstD(gbuf) done before gate writes gbuf
        // ---- gate ----
        {
            const float* bd = b_dil + l * CR_;
            float gb0 = __ldg(bd + c0), gb1 = __ldg(bd + c0 + 1);
            float gb2 = __ldg(bd + c0 + 64), gb3 = __ldg(bd + c0 + 65);
            #pragma unroll
            for (int k = 0; k < 4; ++k) {
                int q = q0 + 32 * k;
                float2 a0 = up2(acc2[0][k]);
                float2 a1 = up2(acc2[1][k]);
                float2 a2v = up2(acc2[2][k]);
                float2 a3v = up2(acc2[3][k]);
                float g0a = tanhf(a0.x + gb0) * sigmoidf_(a2v.x + gb2);
                float g0b = tanhf(a0.y + gb0) * sigmoidf_(a2v.y + gb2);
                float g1a = tanhf(a1.x + gb1) * sigmoidf_(a3v.x + gb3);
                float g1b = tanhf(a1.y + gb1) * sigmoidf_(a3v.y + gb3);
                *reinterpret_cast<u64*>(gbuf + c0 * XS + q)       = pk2(g0a, g0b);
                *reinterpret_cast<u64*>(gbuf + (c0 + 1) * XS + q) = pk2(g1a, g1b);
            }
        }
        __syncthreads();

        // ---- skip accumulation ----
        {
            const float* wsk = w_skip + (size_t)l * CS_ * GC_;
            u64 sacc0[13], sacc1[13];
            #pragma unroll
            for (int kk = 0; kk < 13; ++kk) { sacc0[kk] = 0ULL; sacc1[kk] = 0ULL; }
            for (int gch = 0; gch < 4; ++gch) {
                const int gcb = gch * 16;
                for (int idx = tid; idx < 4096; idx += NT) {
                    int gc = idx & 15; int cs = idx >> 4;
                    wst[gc * 260 + cs] = wsk[cs * GC_ + gcb + gc];
                }
                __syncthreads();
                #pragma unroll
                for (int gc = 0; gc < 16; ++gc) {
                    const float* wrow = wst + gc * 260;
                    u64 wb0 = bc2(wrow[cs0]);
                    u64 wb1 = bc2(wrow[cs0 + 1]);
                    const u64* gr = reinterpret_cast<const u64*>(gbuf + (gcb + gc) * XS + 24 + j0);
                    #pragma unroll
                    for (int kk = 0; kk < 13; ++kk) {
                        u64 gv = gr[kk];
                        fma2(sacc0[kk], wb0, gv);
                        fma2(sacc1[kk], wb1, gv);
                    }
                }
                __syncthreads();
            }
            const float* bsk = b_skip + l * CS_;
            u64 bbp0 = bc2(__ldg(bsk + cs0));
            u64 bbp1 = bc2(__ldg(bsk + cs0 + 1));
            u64* sp0 = reinterpret_cast<u64*>(skipS + cs0 * SKS + j0);
            u64* sp1 = reinterpret_cast<u64*>(skipS + (cs0 + 1) * SKS + j0);
            #pragma unroll
            for (int kk = 0; kk < 13; ++kk) {
                sp0[kk] = add2(sp0[kk], add2(sacc0[kk], bbp0));
                sp1[kk] = add2(sp1[kk], add2(sacc1[kk], bbp1));
            }
        }

        // ---- residual: x = x + W_res g (+b) ----
        {
            const float* wrp = w_res + (size_t)l * CR_ * GC_;
            u64 racc[4][4];
            #pragma unroll
            for (int ic = 0; ic < 4; ++ic)
                #pragma unroll
                for (int k = 0; k < 4; ++k) racc[ic][k] = 0ULL;
            for (int gch = 0; gch < 2; ++gch) {
                const int gcb = gch * 32;
                __syncthreads();
                for (int idx = tid; idx < 4096; idx += NT) {
                    int gc = idx & 31; int co = idx >> 5;
                    wst[gc * 130 + co] = wrp[co * GC_ + gcb + gc];
                }
                __syncthreads();
                #pragma unroll
                for (int gc = 0; gc < 32; ++gc) {
                    const float* grow = gbuf + (gcb + gc) * XS;
                    u64 g0 = *reinterpret_cast<const u64*>(grow + q0);
                    u64 g1 = *reinterpret_cast<const u64*>(grow + q0 + 32);
                    u64 g2 = *reinterpret_cast<const u64*>(grow + q0 + 64);
                    u64 g3 = *reinterpret_cast<const u64*>(grow + q0 + 96);
                    const float* wrow = wst + gc * 130;
                    float2 wlo = *reinterpret_cast<const float2*>(wrow + c0);
                    float2 whi = *reinterpret_cast<const float2*>(wrow + c0 + 64);
                    u64 w0 = bc2(wlo.x), w1 = bc2(wlo.y), w2 = bc2(whi.x), w3 = bc2(whi.y);
                    fma2(racc[0][0], w0, g0); fma2(racc[0][1], w0, g1);
                    fma2(racc[0][2], w0, g2); fma2(racc[0][3], w0, g3);
                    fma2(racc[1][0], w1, g0); fma2(racc[1][1], w1, g1);
                    fma2(racc[1][2], w1, g2); fma2(racc[1][3], w1, g3);
                    fma2(racc[2][0], w2, g0); fma2(racc[2][1], w2, g1);
                    fma2(racc[2][2], w2, g2); fma2(racc[2][3], w2, g3);
                    fma2(racc[3][0], w3, g0); fma2(racc[3][1], w3, g1);
                    fma2(racc[3][2], w3, g2); fma2(racc[3][3], w3, g3);
                }
            }
            __syncthreads();
            const float* br = b_res + l * CR_;
            #pragma unroll
            for (int ic = 0; ic < 4; ++ic) {
                int co = (ic < 2) ? (c0 + ic) : (c0 + 62 + ic);
                u64 bp = bc2(__ldg(br + co));
                #pragma unroll
                for (int k = 0; k < 4; ++k) {
                    int q = q0 + 32 * k;
                    u64* xp_ = reinterpret_cast<u64*>(bufA + co * XS + q);
                    u64 v = add2(*xp_, add2(racc[ic][k], bp));
                    if (q < pzero) v = 0ULL;
                    *xp_ = v;
                }
            }
        }
        __syncthreads();
    }

    // ======================= output head (proven layout) =======================
    for (int i = tid; i < N_SKIP; i += NT) {
        float v = skipS[i] * (1.0f / 12.0f);
        skipS[i] = v > 0.0f ? v : 0.0f;
    }

    float* o1buf = bufA;
    const int c0h = tid >> 1;
    const int jh  = 26 * (tid & 1);

    for (int half = 0; half < 2; ++half) {
        const int jbase = half * 52;
        // ---- out1 ----
        u64 a2p[13];
        #pragma unroll
        for (int kk = 0; kk < 13; ++kk) a2p[kk] = 0ULL;
        for (int kch = 0; kch < 16; ++kch) {
            const int kb = kch * 16;
            __syncthreads();
            for (int idx = tid; idx < 4096; idx += NT) {
                int k = idx & 15; int c = idx >> 4;
                wst[k * 260 + c] = w_out1[c * CS_ + kb + k];
            }
            __syncthreads();
            #pragma unroll 4
            for (int k = 0; k < 16; ++k) {
                u64 wb = bc2(wst[k * 260 + c0h]);
                const u64* sr = reinterpret_cast<const u64*>(skipS + (kb + k) * SKS + jbase + jh);
                #pragma unroll
                for (int kk = 0; kk < 13; ++kk) fma2(a2p[kk], wb, sr[kk]);
            }
        }
        __syncthreads();
        {
            float bi = __ldg(b_out1 + c0h);
            float* op = o1buf + c0h * O1S + jh;
            #pragma unroll
            for (int kk = 0; kk < 13; ++kk) {
                float2 v = up2(a2p[kk]);
                float v0 = v.x + bi; v0 = v0 > 0.0f ? v0 : 0.0f;
                float v1 = v.y + bi; v1 = v1 > 0.0f ? v1 : 0.0f;
                *reinterpret_cast<u64*>(op + 2 * kk) = pk2(v0, v1);
            }
        }
        __syncthreads();
        // ---- out2 ----
        u64 a3p[13];
        #pragma unroll
        for (int kk = 0; kk < 13; ++kk) a3p[kk] = 0ULL;
        for (int kch = 0; kch < 16; ++kch) {
            const int kb = kch * 16;
            __syncthreads();
            for (int idx = tid; idx < 4096; idx += NT) {
                int k = idx & 15; int c = idx >> 4;
                wst[k * 260 + c] = w_out2[c * CS_ + kb + k];
            }
            __syncthreads();
            #pragma unroll 4
            for (int k = 0; k < 16; ++k) {
                u64 wb = bc2(wst[k * 260 + c0h]);
                const u64* orr = reinterpret_cast<const u64*>(o1buf + (kb + k) * O1S + jh);
                #pragma unroll
                for (int kk = 0; kk < 13; ++kk) fma2(a3p[kk], wb, orr[kk]);
            }
        }
        {
            float bo = __ldg(b_out2 + c0h);
            float* orow = out + ((size_t)bb * V_ + c0h) * T_;
            #pragma unroll
            for (int kk = 0; kk < 13; ++kk) {
                int t = t0 + jbase + jh + 2 * kk;
                float2 v = up2(a3p[kk]);
                v.x += bo; v.y += bo;
                if (t + 1 < T_) {
                    *reinterpret_cast<float2*>(orow + t) = v;
                } else if (t < T_) {
                    orow[t] = v.x;
                }
            }
        }
        __syncthreads();
    }
}

extern "C" void kernel_launch(void* const* d_in, const int* in_sizes, int n_in,
                              void* d_out, int out_size) {
    const int*   tokens = (const int*)  d_in[0];
    const float* emb    = (const float*)d_in[1];
    const float* w_init = (const float*)d_in[2];
    const float* b_init = (const float*)d_in[3];
    const float* w_dil  = (const float*)d_in[4];
    const float* b_dil  = (const float*)d_in[5];
    const float* w_res  = (const float*)d_in[6];
    const float* b_res  = (const float*)d_in[7];
    const float* w_skip = (const float*)d_in[8];
    const float* b_skip = (const float*)d_in[9];
    const float* w_out1 = (const float*)d_in[10];
    const float* b_out1 = (const float*)d_in[11];
    const float* w_out2 = (const float*)d_in[12];
    const float* b_out2 = (const float*)d_in[13];
    float* out = (float*)d_out;

    cudaFuncSetAttribute(wavenet_fused, cudaFuncAttributeMaxDynamicSharedMemorySize, SMEM_BYTES);
    dim3 grid((T_ + TT - 1) / TT, B_);
    wavenet_fused<<<grid, NT, SMEM_BYTES>>>(
        tokens, emb, w_init, b_init, w_dil, b_dil, w_res, b_res,
        w_skip, b_skip, w_out1, b_out1, w_out2, b_out2, out);
}

// round 15
// speedup vs baseline: 2.2380x; 1.2574x over previous
#include <cuda_runtime.h>
#include <cuda_bf16.h>
#include <math.h>
#include <stdint.h>

// Problem constants
#define B_   16
#define T_   8192
#define V_   256
#define CE_  256
#define CR_  128
#define CS_  256
#define GC_  64
#define L_   12

// Tiling
#define TT   104
#define WP   128
#define XS   132     // gbuf row stride
#define XSA  136     // bufA row stride (conflict-free MMA B loads)
#define XOFF 2       // left pad in bufA rows: slot (XOFF+q) holds x[q], slots 0,1 = x[-2],x[-1]=0
#define SKS  106
#define NT   512
#define O1S  56

// smem layout (floats)
#define OFF_BUFA 0
#define N_BUFA   (128*XSA)            // 17408
#define OFF_GBUF (OFF_BUFA + N_BUFA)
#define N_GBUF   (64*XS)              // 8448; conv tf32-weight staging overlay (64*132=8448)
#define OFF_SKIP (OFF_GBUF + N_GBUF)
#define N_SKIP   (CS_*SKS)
#define OFF_WST  (OFF_SKIP + N_SKIP)
#define N_WST    4224
#define OFF_TOK  (OFF_WST + N_WST)
#define SMEM_BYTES ((OFF_TOK)*4 + 132*4)

typedef unsigned long long u64;

__device__ __forceinline__ u64 pk2(float lo, float hi) {
    u64 r; asm("mov.b64 %0, {%1,%2};" : "=l"(r) : "f"(lo), "f"(hi)); return r;
}
__device__ __forceinline__ u64 bc2(float x) { return pk2(x, x); }
__device__ __forceinline__ void fma2(u64& d, u64 a, u64 b) {
    asm("fma.rn.f32x2 %0, %1, %2, %0;" : "+l"(d) : "l"(a), "l"(b));
}
__device__ __forceinline__ u64 add2(u64 a, u64 b) {
    u64 r; asm("add.rn.f32x2 %0, %1, %2;" : "=l"(r) : "l"(a), "l"(b)); return r;
}
__device__ __forceinline__ float2 up2(u64 a) {
    float2 f; asm("mov.b64 {%0,%1}, %2;" : "=f"(f.x), "=f"(f.y) : "l"(a)); return f;
}
__device__ __forceinline__ float sigmoidf_(float x) {
    return __fdividef(1.0f, 1.0f + __expf(-x));
}
__device__ __forceinline__ float tanhf_(float x) {
    return 1.0f - __fdividef(2.0f, __expf(2.0f * x) + 1.0f);
}
__device__ __forceinline__ uint32_t tf32_(float f) {
    uint32_t u; asm("cvt.rna.tf32.f32 %0, %1;" : "=r"(u) : "f"(f)); return u;
}
__device__ __forceinline__ void mma_tf32(float* d,
    uint32_t a0, uint32_t a1, uint32_t a2, uint32_t a3, uint32_t b0, uint32_t b1) {
    asm volatile(
        "mma.sync.aligned.m16n8k8.row.col.f32.tf32.tf32.f32 "
        "{%0,%1,%2,%3},{%4,%5,%6,%7},{%8,%9},{%0,%1,%2,%3};"
        : "+f"(d[0]), "+f"(d[1]), "+f"(d[2]), "+f"(d[3])
        : "r"(a0), "r"(a1), "r"(a2), "r"(a3), "r"(b0), "r"(b1));
}

__global__ void __launch_bounds__(NT, 1) wavenet_fused(
    const int*   __restrict__ tokens,
    const float* __restrict__ emb,
    const float* __restrict__ w_init, const float* __restrict__ b_init,
    const float* __restrict__ w_dil,  const float* __restrict__ b_dil,
    const float* __restrict__ w_res,  const float* __restrict__ b_res,
    const float* __restrict__ w_skip, const float* __restrict__ b_skip,
    const float* __restrict__ w_out1, const float* __restrict__ b_out1,
    const float* __restrict__ w_out2, const float* __restrict__ b_out2,
    float* __restrict__ out)
{
    extern __shared__ float sm[];
    float* bufA  = sm + OFF_BUFA;   // x activations [128][XSA], x[q] at col XOFF+q
    float* gbuf  = sm + OFF_GBUF;   // gate output [64][XS]; conv tf32-weight staging overlay
    float* skipS = sm + OFF_SKIP;   // skip accum [256][SKS]
    float* wst   = sm + OFF_WST;    // small weight staging
    int*   tokb  = (int*)(sm + OFF_TOK);

    const int tid  = threadIdx.x;
    const int tile = blockIdx.x;
    const int bb   = blockIdx.y;
    const int t0   = tile * TT;
    const int pzero = (tile == 0) ? 24 : 0;

    for (int q = tid; q < WP + 1; q += NT) {
        int t = t0 - 25 + q;
        tokb[q] = (t >= 0 && t < T_) ? tokens[bb * T_ + t] : -1;
    }
    for (int i = tid; i < N_SKIP; i += NT) skipS[i] = 0.0f;
    // zero the 2-float left pads of bufA rows (x[-2],x[-1])
    for (int r = tid; r < 128; r += NT) {
        bufA[r * XSA]     = 0.0f;
        bufA[r * XSA + 1] = 0.0f;
    }

    // scalar mapping (init conv / residual): 4 channels x 4 strided pairs
    const int cg = tid >> 4;
    const int pg = tid & 15;
    const int c0 = 2 * cg;
    const int q0 = 2 * pg;

    // MMA mapping
    const int warp = tid >> 5;           // 0..15
    const int lane = tid & 31;
    const int gid  = lane >> 2;          // 0..7
    const int tig  = lane & 3;           // 0..3
    const int m0   = (warp >> 1) << 4;   // co block of 16
    const int n0   = (warp & 1) << 6;    // p half of 64

    // ======================= init conv (emb -> x0) =======================
    {
        u64 acc[4][4];
        #pragma unroll
        for (int ic = 0; ic < 4; ++ic)
            #pragma unroll
            for (int k = 0; k < 4; ++k) acc[ic][k] = 0ULL;

        __syncthreads();
        for (int ch = 0; ch < 16; ++ch) {       // ce chunks of 16
            const int ceb = ch * 16;
            for (int idx = tid; idx < (WP + 1) * 4; idx += NT) {
                int q = idx >> 2; int ce4 = (idx & 3) << 2;
                int tok = tokb[q];
                float4 v = make_float4(0.f, 0.f, 0.f, 0.f);
                if (tok >= 0) v = *reinterpret_cast<const float4*>(emb + tok * CE_ + ceb + ce4);
                gbuf[(ce4 + 0) * XS + q] = v.x;
                gbuf[(ce4 + 1) * XS + q] = v.y;
                gbuf[(ce4 + 2) * XS + q] = v.z;
                gbuf[(ce4 + 3) * XS + q] = v.w;
            }
            for (int idx = tid; idx < 2048; idx += NT) {
                int ce = idx & 15; int co = idx >> 4;
                float2 w2 = *reinterpret_cast<const float2*>(w_init + ((co * CE_ + ceb + ce) << 1));
                wst[ce * 260 + co]       = w2.x;
                wst[ce * 260 + 128 + co] = w2.y;
            }
            __syncthreads();
            #pragma unroll
            for (int ce = 0; ce < 16; ++ce) {
                const float* hr = gbuf + ce * XS;
                const float* wr = wst + ce * 260;
                u64 w00 = bc2(wr[c0]),        w10 = bc2(wr[128 + c0]);
                u64 w01 = bc2(wr[c0 + 1]),    w11 = bc2(wr[128 + c0 + 1]);
                u64 w02 = bc2(wr[c0 + 64]),   w12 = bc2(wr[128 + c0 + 64]);
                u64 w03 = bc2(wr[c0 + 65]),   w13 = bc2(wr[128 + c0 + 65]);
                #pragma unroll
                for (int k = 0; k < 4; ++k) {
                    int q = q0 + 32 * k;
                    u64 A = *reinterpret_cast<const u64*>(hr + q);
                    float s = hr[q + 2];
                    float2 av = up2(A);
                    u64 T1 = pk2(av.y, s);
                    fma2(acc[0][k], w00, A); fma2(acc[0][k], w10, T1);
                    fma2(acc[1][k], w01, A); fma2(acc[1][k], w11, T1);
                    fma2(acc[2][k], w02, A); fma2(acc[2][k], w12, T1);
                    fma2(acc[3][k], w03, A); fma2(acc[3][k], w13, T1);
                }
            }
            __syncthreads();
        }
        #pragma unroll
        for (int ic = 0; ic < 4; ++ic) {
            int co = (ic < 2) ? (c0 + ic) : (c0 + 62 + ic);
            u64 bp = bc2(__ldg(b_init + co));
            #pragma unroll
            for (int k = 0; k < 4; ++k) {
                int q = q0 + 32 * k;
                u64 v = (q < pzero) ? 0ULL : add2(acc[ic][k], bp);
                *reinterpret_cast<u64*>(bufA + co * XSA + XOFF + q) = v;
            }
        }
    }
    __syncthreads();

    // skip mapping (proven): 2 cs channels x 13 pairs
    const int cs0 = 2 * (tid >> 2);
    const int j0  = 26 * (tid & 3);

    float* wstD = gbuf;   // conv tf32 weight staging overlays gbuf: row kk (64) x 132, [kk][co]

    // ============================ layers ============================
    for (int l = 0; l < L_; ++l) {
        // ---- dilated conv via tensor-core tf32 MMA ----
        // xc[co][p] = sum_{ci,tap} W[co][ci][tap] * x[ci][p-2+2*tap], p in [0,128)
        float d[8][4];
        #pragma unroll
        for (int nb = 0; nb < 8; ++nb)
            #pragma unroll
            for (int e = 0; e < 4; ++e) d[nb][e] = 0.0f;

        const float* wd = w_dil + (size_t)l * CR_ * CR_ * 2;
        for (int ch = 0; ch < 4; ++ch) {        // K chunks: 32 ci x 2 taps = 64 kk
            const int cib = ch * 32;
            __syncthreads();   // staging buffer free (prev consumers done)
            for (int idx = tid; idx < 4096; idx += NT) {
                int ci = idx & 31; int co = idx >> 5;
                float2 w2 = *reinterpret_cast<const float2*>(wd + ((co * CR_ + cib + ci) << 1));
                wstD[ci * 132 + co]        = __uint_as_float(tf32_(w2.x));   // kk=ci (tap0)
                wstD[(32 + ci) * 132 + co] = __uint_as_float(tf32_(w2.y));   // kk=32+ci (tap1)
            }
            __syncthreads();
            #pragma unroll
            for (int s = 0; s < 8; ++s) {
                const int kk0 = 8 * s;
                uint32_t a0 = __float_as_uint(wstD[(kk0 + tig) * 132 + m0 + gid]);
                uint32_t a1 = __float_as_uint(wstD[(kk0 + tig) * 132 + m0 + gid + 8]);
                uint32_t a2 = __float_as_uint(wstD[(kk0 + tig + 4) * 132 + m0 + gid]);
                uint32_t a3 = __float_as_uint(wstD[(kk0 + tig + 4) * 132 + m0 + gid + 8]);
                const int ciA = cib + ((s < 4) ? (kk0 + tig) : (kk0 - 32 + tig));
                const int tp  = (s < 4) ? 0 : 2;    // tap0: slot p = x[p-2]; tap1: slot p+2 = x[p]
                const float* xr0 = bufA + ciA * XSA + tp + n0 + gid;
                const float* xr1 = xr0 + 4 * XSA;
                #pragma unroll
                for (int nb = 0; nb < 8; ++nb) {
                    uint32_t b0 = tf32_(xr0[8 * nb]);
                    uint32_t b1 = tf32_(xr1[8 * nb]);
                    mma_tf32(d[nb], a0, a1, a2, a3, b0, b1);
                }
            }
        }
        __syncthreads();   // conv reads of wstD(gbuf)/bufA done

        // ---- gate: upper warps park xc_hi(+bias) in gbuf; lower warps gate in place ----
        const float* bd = b_dil + l * CR_;
        if (warp >= 8) {
            int coU = m0 + gid;                     // 64..127
            float bH  = __ldg(bd + coU);
            float bH2 = __ldg(bd + coU + 8);
            #pragma unroll
            for (int nb = 0; nb < 8; ++nb) {
                int p = n0 + 8 * nb + 2 * tig;
                *reinterpret_cast<float2*>(gbuf + (coU - 64) * XS + p) =
                    make_float2(d[nb][0] + bH, d[nb][1] + bH);
                *reinterpret_cast<float2*>(gbuf + (coU - 64 + 8) * XS + p) =
                    make_float2(d[nb][2] + bH2, d[nb][3] + bH2);
            }
        }
        __syncthreads();
        if (warp < 8) {
            int co = m0 + gid;                      // 0..63
            float bL  = __ldg(bd + co);
            float bL2 = __ldg(bd + co + 8);
            #pragma unroll
            for (int nb = 0; nb < 8; ++nb) {
                int p = n0 + 8 * nb + 2 * tig;
                float2 u1 = *reinterpret_cast<const float2*>(gbuf + co * XS + p);
                float2 u2 = *reinterpret_cast<const float2*>(gbuf + (co + 8) * XS + p);
                float g0 = tanhf_(d[nb][0] + bL)  * sigmoidf_(u1.x);
                float g1 = tanhf_(d[nb][1] + bL)  * sigmoidf_(u1.y);
                float g2 = tanhf_(d[nb][2] + bL2) * sigmoidf_(u2.x);
                float g3 = tanhf_(d[nb][3] + bL2) * sigmoidf_(u2.y);
                *reinterpret_cast<float2*>(gbuf + co * XS + p)       = make_float2(g0, g1);
                *reinterpret_cast<float2*>(gbuf + (co + 8) * XS + p) = make_float2(g2, g3);
            }
        }
        __syncthreads();

        // ---- skip accumulation (proven) ----
        {
            const float* wsk = w_skip + (size_t)l * CS_ * GC_;
            u64 sacc0[13], sacc1[13];
            #pragma unroll
            for (int kk = 0; kk < 13; ++kk) { sacc0[kk] = 0ULL; sacc1[kk] = 0ULL; }
            for (int gch = 0; gch < 4; ++gch) {
                const int gcb = gch * 16;
                for (int idx = tid; idx < 4096; idx += NT) {
                    int gc = idx & 15; int cs = idx >> 4;
                    wst[gc * 260 + cs] = wsk[cs * GC_ + gcb + gc];
                }
                __syncthreads();
                #pragma unroll
                for (int gc = 0; gc < 16; ++gc) {
                    const float* wrow = wst + gc * 260;
                    u64 wb0 = bc2(wrow[cs0]);
                    u64 wb1 = bc2(wrow[cs0 + 1]);
                    const u64* gr = reinterpret_cast<const u64*>(gbuf + (gcb + gc) * XS + 24 + j0);
                    #pragma unroll
                    for (int kk = 0; kk < 13; ++kk) {
                        u64 gv = gr[kk];
                        fma2(sacc0[kk], wb0, gv);
                        fma2(sacc1[kk], wb1, gv);
                    }
                }
                __syncthreads();
            }
            const float* bsk = b_skip + l * CS_;
            u64 bbp0 = bc2(__ldg(bsk + cs0));
            u64 bbp1 = bc2(__ldg(bsk + cs0 + 1));
            u64* sp0 = reinterpret_cast<u64*>(skipS + cs0 * SKS + j0);
            u64* sp1 = reinterpret_cast<u64*>(skipS + (cs0 + 1) * SKS + j0);
            #pragma unroll
            for (int kk = 0; kk < 13; ++kk) {
                sp0[kk] = add2(sp0[kk], add2(sacc0[kk], bbp0));
                sp1[kk] = add2(sp1[kk], add2(sacc1[kk], bbp1));
            }
        }

        // ---- residual: x = x + W_res g (+b) (proven, bufA at XOFF) ----
        {
            const float* wrp = w_res + (size_t)l * CR_ * GC_;
            u64 racc[4][4];
            #pragma unroll
            for (int ic = 0; ic < 4; ++ic)
                #pragma unroll
                for (int k = 0; k < 4; ++k) racc[ic][k] = 0ULL;
            for (int gch = 0; gch < 2; ++gch) {
                const int gcb = gch * 32;
                __syncthreads();
                for (int idx = tid; idx < 4096; idx += NT) {
                    int gc = idx & 31; int co = idx >> 5;
                    wst[gc * 130 + co] = wrp[co * GC_ + gcb + gc];
                }
                __syncthreads();
                #pragma unroll
                for (int gc = 0; gc < 32; ++gc) {
                    const float* grow = gbuf + (gcb + gc) * XS;
                    u64 g0 = *reinterpret_cast<const u64*>(grow + q0);
                    u64 g1 = *reinterpret_cast<const u64*>(grow + q0 + 32);
                    u64 g2 = *reinterpret_cast<const u64*>(grow + q0 + 64);
                    u64 g3 = *reinterpret_cast<const u64*>(grow + q0 + 96);
                    const float* wrow = wst + gc * 130;
                    float2 wlo = *reinterpret_cast<const float2*>(wrow + c0);
                    float2 whi = *reinterpret_cast<const float2*>(wrow + c0 + 64);
                    u64 w0 = bc2(wlo.x), w1 = bc2(wlo.y), w2 = bc2(whi.x), w3 = bc2(whi.y);
                    fma2(racc[0][0], w0, g0); fma2(racc[0][1], w0, g1);
                    fma2(racc[0][2], w0, g2); fma2(racc[0][3], w0, g3);
                    fma2(racc[1][0], w1, g0); fma2(racc[1][1], w1, g1);
                    fma2(racc[1][2], w1, g2); fma2(racc[1][3], w1, g3);
                    fma2(racc[2][0], w2, g0); fma2(racc[2][1], w2, g1);
                    fma2(racc[2][2], w2, g2); fma2(racc[2][3], w2, g3);
                    fma2(racc[3][0], w3, g0); fma2(racc[3][1], w3, g1);
                    fma2(racc[3][2], w3, g2); fma2(racc[3][3], w3, g3);
                }
            }
            __syncthreads();
            const float* br = b_res + l * CR_;
            #pragma unroll
            for (int ic = 0; ic < 4; ++ic) {
                int co = (ic < 2) ? (c0 + ic) : (c0 + 62 + ic);
                u64 bp = bc2(__ldg(br + co));
                #pragma unroll
                for (int k = 0; k < 4; ++k) {
                    int q = q0 + 32 * k;
                    u64* xp_ = reinterpret_cast<u64*>(bufA + co * XSA + XOFF + q);
                    u64 v = add2(*xp_, add2(racc[ic][k], bp));
                    if (q < pzero) v = 0ULL;
                    *xp_ = v;
                }
            }
        }
        __syncthreads();
    }

    // ======================= output head (proven layout) =======================
    for (int i = tid; i < N_SKIP; i += NT) {
        float v = skipS[i] * (1.0f / 12.0f);
        skipS[i] = v > 0.0f ? v : 0.0f;
    }

    float* o1buf = bufA;
    const int c0h = tid >> 1;
    const int jh  = 26 * (tid & 1);

    for (int half = 0; half < 2; ++half) {
        const int jbase = half * 52;
        // ---- out1 ----
        u64 a2p[13];
        #pragma unroll
        for (int kk = 0; kk < 13; ++kk) a2p[kk] = 0ULL;
        for (int kch = 0; kch < 16; ++kch) {
            const int kb = kch * 16;
            __syncthreads();
            for (int idx = tid; idx < 4096; idx += NT) {
                int k = idx & 15; int c = idx >> 4;
                wst[k * 260 + c] = w_out1[c * CS_ + kb + k];
            }
            __syncthreads();
            #pragma unroll 4
            for (int k = 0; k < 16; ++k) {
                u64 wb = bc2(wst[k * 260 + c0h]);
                const u64* sr = reinterpret_cast<const u64*>(skipS + (kb + k) * SKS + jbase + jh);
                #pragma unroll
                for (int kk = 0; kk < 13; ++kk) fma2(a2p[kk], wb, sr[kk]);
            }
        }
        __syncthreads();
        {
            float bi = __ldg(b_out1 + c0h);
            float* op = o1buf + c0h * O1S + jh;
            #pragma unroll
            for (int kk = 0; kk < 13; ++kk) {
                float2 v = up2(a2p[kk]);
                float v0 = v.x + bi; v0 = v0 > 0.0f ? v0 : 0.0f;
                float v1 = v.y + bi; v1 = v1 > 0.0f ? v1 : 0.0f;
                *reinterpret_cast<u64*>(op + 2 * kk) = pk2(v0, v1);
            }
        }
        __syncthreads();
        // ---- out2 ----
        u64 a3p[13];
        #pragma unroll
        for (int kk = 0; kk < 13; ++kk) a3p[kk] = 0ULL;
        for (int kch = 0; kch < 16; ++kch) {
            const int kb = kch * 16;
            __syncthreads();
            for (int idx = tid; idx < 4096; idx += NT) {
                int k = idx & 15; int c = idx >> 4;
                wst[k * 260 + c] = w_out2[c * CS_ + kb + k];
            }
            __syncthreads();
            #pragma unroll 4
            for (int k = 0; k < 16; ++k) {
                u64 wb = bc2(wst[k * 260 + c0h]);
                const u64* orr = reinterpret_cast<const u64*>(o1buf + (kb + k) * O1S + jh);
                #pragma unroll
                for (int kk = 0; kk < 13; ++kk) fma2(a3p[kk], wb, orr[kk]);
            }
        }
        {
            float bo = __ldg(b_out2 + c0h);
            float* orow = out + ((size_t)bb * V_ + c0h) * T_;
            #pragma unroll
            for (int kk = 0; kk < 13; ++kk) {
                int t = t0 + jbase + jh + 2 * kk;
                float2 v = up2(a3p[kk]);
                v.x += bo; v.y += bo;
                if (t + 1 < T_) {
                    *reinterpret_cast<float2*>(orow + t) = v;
                } else if (t < T_) {
                    orow[t] = v.x;
                }
            }
        }
        __syncthreads();
    }
}

extern "C" void kernel_launch(void* const* d_in, const int* in_sizes, int n_in,
                              void* d_out, int out_size) {
    const int*   tokens = (const int*)  d_in[0];
    const float* emb    = (const float*)d_in[1];
    const float* w_init = (const float*)d_in[2];
    const float* b_init = (const float*)d_in[3];
    const float* w_dil  = (const float*)d_in[4];
    const float* b_dil  = (const float*)d_in[5];
    const float* w_res  = (const float*)d_in[6];
    const float* b_res  = (const float*)d_in[7];
    const float* w_skip = (const float*)d_in[8];
    const float* b_skip = (const float*)d_in[9];
    const float* w_out1 = (const float*)d_in[10];
    const float* b_out1 = (const float*)d_in[11];
    const float* w_out2 = (const float*)d_in[12];
    const float* b_out2 = (const float*)d_in[13];
    float* out = (float*)d_out;

    cudaFuncSetAttribute(wavenet_fused, cudaFuncAttributeMaxDynamicSharedMemorySize, SMEM_BYTES);
    dim3 grid((T_ + TT - 1) / TT, B_);
    wavenet_fused<<<grid, NT, SMEM_BYTES>>>(
        tokens, emb, w_init, b_init, w_dil, b_dil, w_res, b_res,
        w_skip, b_skip, w_out1, b_out1, w_out2, b_out2, out);
}

// round 16
// speedup vs baseline: 2.8736x; 1.2840x over previous
#include <cuda_runtime.h>
#include <cuda_bf16.h>
#include <math.h>
#include <stdint.h>

// Problem constants
#define B_   16
#define T_   8192
#define V_   256
#define CE_  256
#define CR_  128
#define CS_  256
#define GC_  64
#define L_   12

// Tiling
#define TT   104
#define WP   128
#define GXS  136     // gbuf row stride (conflict-free MMA B loads)
#define XSA  136     // bufA row stride
#define XOFF 2       // left pad: slot (XOFF+q) holds x[q]; slots 0,1 = x[-2],x[-1]=0
#define SKS  106
#define NT   512
#define O1S  56

// smem layout (floats)
#define OFF_BUFA 0
#define N_BUFA   (128*XSA)            // 17408
#define OFF_GBUF (OFF_BUFA + N_BUFA)
#define N_GBUF   (64*GXS)             // 8704; conv tf32-weight staging overlay (64*136)
#define OFF_SKIP (OFF_GBUF + N_GBUF)
#define N_SKIP   (CS_*SKS)            // 27136
#define OFF_WST  (OFF_SKIP + N_SKIP)
#define N_WST    4224
#define OFF_TOK  (OFF_WST + N_WST)
#define SMEM_BYTES ((OFF_TOK)*4 + 132*4)   // 230,416 B

typedef unsigned long long u64;

__device__ __forceinline__ u64 pk2(float lo, float hi) {
    u64 r; asm("mov.b64 %0, {%1,%2};" : "=l"(r) : "f"(lo), "f"(hi)); return r;
}
__device__ __forceinline__ u64 bc2(float x) { return pk2(x, x); }
__device__ __forceinline__ void fma2(u64& d, u64 a, u64 b) {
    asm("fma.rn.f32x2 %0, %1, %2, %0;" : "+l"(d) : "l"(a), "l"(b));
}
__device__ __forceinline__ u64 add2(u64 a, u64 b) {
    u64 r; asm("add.rn.f32x2 %0, %1, %2;" : "=l"(r) : "l"(a), "l"(b)); return r;
}
__device__ __forceinline__ float2 up2(u64 a) {
    float2 f; asm("mov.b64 {%0,%1}, %2;" : "=f"(f.x), "=f"(f.y) : "l"(a)); return f;
}
__device__ __forceinline__ float sigmoidf_(float x) {
    return __fdividef(1.0f, 1.0f + __expf(-x));
}
__device__ __forceinline__ float tanhf_(float x) {
    return 1.0f - __fdividef(2.0f, __expf(2.0f * x) + 1.0f);
}
__device__ __forceinline__ uint32_t tf32_(float f) {
    uint32_t u; asm("cvt.rna.tf32.f32 %0, %1;" : "=r"(u) : "f"(f)); return u;
}
__device__ __forceinline__ void mma_tf32(float* d,
    uint32_t a0, uint32_t a1, uint32_t a2, uint32_t a3, uint32_t b0, uint32_t b1) {
    asm volatile(
        "mma.sync.aligned.m16n8k8.row.col.f32.tf32.tf32.f32 "
        "{%0,%1,%2,%3},{%4,%5,%6,%7},{%8,%9},{%0,%1,%2,%3};"
        : "+f"(d[0]), "+f"(d[1]), "+f"(d[2]), "+f"(d[3])
        : "r"(a0), "r"(a1), "r"(a2), "r"(a3), "r"(b0), "r"(b1));
}

__global__ void __launch_bounds__(NT, 1) wavenet_fused(
    const int*   __restrict__ tokens,
    const float* __restrict__ emb,
    const float* __restrict__ w_init, const float* __restrict__ b_init,
    const float* __restrict__ w_dil,  const float* __restrict__ b_dil,
    const float* __restrict__ w_res,  const float* __restrict__ b_res,
    const float* __restrict__ w_skip, const float* __restrict__ b_skip,
    const float* __restrict__ w_out1, const float* __restrict__ b_out1,
    const float* __restrict__ w_out2, const float* __restrict__ b_out2,
    float* __restrict__ out)
{
    extern __shared__ float sm[];
    float* bufA  = sm + OFF_BUFA;   // x activations [128][XSA], x[q] at col XOFF+q
    float* gbuf  = sm + OFF_GBUF;   // gate output (tf32 bits) [64][GXS]; conv weight overlay
    float* skipS = sm + OFF_SKIP;   // skip accum [256][SKS]
    float* wst   = sm + OFF_WST;    // small weight staging
    int*   tokb  = (int*)(sm + OFF_TOK);

    const int tid  = threadIdx.x;
    const int tile = blockIdx.x;
    const int bb   = blockIdx.y;
    const int t0   = tile * TT;
    const int pzero = (tile == 0) ? 24 : 0;

    for (int q = tid; q < WP + 1; q += NT) {
        int t = t0 - 25 + q;
        tokb[q] = (t >= 0 && t < T_) ? tokens[bb * T_ + t] : -1;
    }
    for (int i = tid; i < N_SKIP; i += NT) skipS[i] = 0.0f;
    for (int r = tid; r < 128; r += NT) {
        bufA[r * XSA]     = 0.0f;
        bufA[r * XSA + 1] = 0.0f;
    }

    // scalar mapping (init conv only): 4 channels x 4 strided pairs
    const int cg = tid >> 4;
    const int pg = tid & 15;
    const int c0 = 2 * cg;
    const int q0 = 2 * pg;

    // MMA mapping
    const int warp = tid >> 5;           // 0..15
    const int lane = tid & 31;
    const int gid  = lane >> 2;          // 0..7
    const int tig  = lane & 3;           // 0..3
    const int m0   = (warp >> 1) << 4;   // conv/res: co block of 16
    const int n0   = (warp & 1) << 6;    // conv/res: p half of 64
    const int m0s  = warp << 4;          // skip: cs block of 16 (0..240)

    // ======================= init conv (emb -> x0) =======================
    {
        u64 acc[4][4];
        #pragma unroll
        for (int ic = 0; ic < 4; ++ic)
            #pragma unroll
            for (int k = 0; k < 4; ++k) acc[ic][k] = 0ULL;

        __syncthreads();
        for (int ch = 0; ch < 16; ++ch) {       // ce chunks of 16
            const int ceb = ch * 16;
            for (int idx = tid; idx < (WP + 1) * 4; idx += NT) {
                int q = idx >> 2; int ce4 = (idx & 3) << 2;
                int tok = tokb[q];
                float4 v = make_float4(0.f, 0.f, 0.f, 0.f);
                if (tok >= 0) v = *reinterpret_cast<const float4*>(emb + tok * CE_ + ceb + ce4);
                gbuf[(ce4 + 0) * GXS + q] = v.x;
                gbuf[(ce4 + 1) * GXS + q] = v.y;
                gbuf[(ce4 + 2) * GXS + q] = v.z;
                gbuf[(ce4 + 3) * GXS + q] = v.w;
            }
            for (int idx = tid; idx < 2048; idx += NT) {
                int ce = idx & 15; int co = idx >> 4;
                float2 w2 = *reinterpret_cast<const float2*>(w_init + ((co * CE_ + ceb + ce) << 1));
                wst[ce * 260 + co]       = w2.x;
                wst[ce * 260 + 128 + co] = w2.y;
            }
            __syncthreads();
            #pragma unroll
            for (int ce = 0; ce < 16; ++ce) {
                const float* hr = gbuf + ce * GXS;
                const float* wr = wst + ce * 260;
                u64 w00 = bc2(wr[c0]),        w10 = bc2(wr[128 + c0]);
                u64 w01 = bc2(wr[c0 + 1]),    w11 = bc2(wr[128 + c0 + 1]);
                u64 w02 = bc2(wr[c0 + 64]),   w12 = bc2(wr[128 + c0 + 64]);
                u64 w03 = bc2(wr[c0 + 65]),   w13 = bc2(wr[128 + c0 + 65]);
                #pragma unroll
                for (int k = 0; k < 4; ++k) {
                    int q = q0 + 32 * k;
                    u64 A = *reinterpret_cast<const u64*>(hr + q);
                    float s = hr[q + 2];
                    float2 av = up2(A);
                    u64 T1 = pk2(av.y, s);
                    fma2(acc[0][k], w00, A); fma2(acc[0][k], w10, T1);
                    fma2(acc[1][k], w01, A); fma2(acc[1][k], w11, T1);
                    fma2(acc[2][k], w02, A); fma2(acc[2][k], w12, T1);
                    fma2(acc[3][k], w03, A); fma2(acc[3][k], w13, T1);
                }
            }
            __syncthreads();
        }
        #pragma unroll
        for (int ic = 0; ic < 4; ++ic) {
            int co = (ic < 2) ? (c0 + ic) : (c0 + 62 + ic);
            u64 bp = bc2(__ldg(b_init + co));
            #pragma unroll
            for (int k = 0; k < 4; ++k) {
                int q = q0 + 32 * k;
                u64 v = (q < pzero) ? 0ULL : add2(acc[ic][k], bp);
                *reinterpret_cast<u64*>(bufA + co * XSA + XOFF + q) = v;
            }
        }
    }
    __syncthreads();

    float* wstD = gbuf;   // conv tf32 weight staging overlays gbuf: [kk(64)][136] = [kk][co]

    // ============================ layers ============================
    for (int l = 0; l < L_; ++l) {
        // ---- dilated conv via tensor MMA ----
        float d[8][4];
        #pragma unroll
        for (int nb = 0; nb < 8; ++nb)
            #pragma unroll
            for (int e = 0; e < 4; ++e) d[nb][e] = 0.0f;

        const float* wd = w_dil + (size_t)l * CR_ * CR_ * 2;
        for (int ch = 0; ch < 4; ++ch) {        // K chunks: 32 ci x 2 taps = 64 kk
            const int cib = ch * 32;
            __syncthreads();
            for (int idx = tid; idx < 4096; idx += NT) {
                int ci = idx & 31; int co = idx >> 5;
                float2 w2 = *reinterpret_cast<const float2*>(wd + ((co * CR_ + cib + ci) << 1));
                wstD[ci * GXS + co]        = __uint_as_float(tf32_(w2.x));   // tap0
                wstD[(32 + ci) * GXS + co] = __uint_as_float(tf32_(w2.y));   // tap1
            }
            __syncthreads();
            #pragma unroll
            for (int s = 0; s < 8; ++s) {
                const int kk0 = 8 * s;
                uint32_t a0 = __float_as_uint(wstD[(kk0 + tig) * GXS + m0 + gid]);
                uint32_t a1 = __float_as_uint(wstD[(kk0 + tig) * GXS + m0 + gid + 8]);
                uint32_t a2 = __float_as_uint(wstD[(kk0 + tig + 4) * GXS + m0 + gid]);
                uint32_t a3 = __float_as_uint(wstD[(kk0 + tig + 4) * GXS + m0 + gid + 8]);
                const int ciA = cib + ((s < 4) ? (kk0 + tig) : (kk0 - 32 + tig));
                const int tp  = (s < 4) ? 0 : 2;
                const float* xr0 = bufA + ciA * XSA + tp + n0 + gid;
                const float* xr1 = xr0 + 4 * XSA;
                #pragma unroll
                for (int nb = 0; nb < 8; ++nb) {
                    uint32_t b0 = tf32_(xr0[8 * nb]);
                    uint32_t b1 = tf32_(xr1[8 * nb]);
                    mma_tf32(d[nb], a0, a1, a2, a3, b0, b1);
                }
            }
        }
        __syncthreads();

        // ---- gate: upper warps park xc_hi(+bias); lower warps gate; g stored as tf32 bits ----
        const float* bd = b_dil + l * CR_;
        if (warp >= 8) {
            int coU = m0 + gid;                     // 64..127
            float bH  = __ldg(bd + coU);
            float bH2 = __ldg(bd + coU + 8);
            #pragma unroll
            for (int nb = 0; nb < 8; ++nb) {
                int p = n0 + 8 * nb + 2 * tig;
                *reinterpret_cast<float2*>(gbuf + (coU - 64) * GXS + p) =
                    make_float2(d[nb][0] + bH, d[nb][1] + bH);
                *reinterpret_cast<float2*>(gbuf + (coU - 64 + 8) * GXS + p) =
                    make_float2(d[nb][2] + bH2, d[nb][3] + bH2);
            }
        }
        __syncthreads();
        if (warp < 8) {
            int co = m0 + gid;                      // 0..63
            float bL  = __ldg(bd + co);
            float bL2 = __ldg(bd + co + 8);
            #pragma unroll
            for (int nb = 0; nb < 8; ++nb) {
                int p = n0 + 8 * nb + 2 * tig;
                float2 u1 = *reinterpret_cast<const float2*>(gbuf + co * GXS + p);
                float2 u2 = *reinterpret_cast<const float2*>(gbuf + (co + 8) * GXS + p);
                float g0 = tanhf_(d[nb][0] + bL)  * sigmoidf_(u1.x);
                float g1 = tanhf_(d[nb][1] + bL)  * sigmoidf_(u1.y);
                float g2 = tanhf_(d[nb][2] + bL2) * sigmoidf_(u2.x);
                float g3 = tanhf_(d[nb][3] + bL2) * sigmoidf_(u2.y);
                *reinterpret_cast<float2*>(gbuf + co * GXS + p) =
                    make_float2(__uint_as_float(tf32_(g0)), __uint_as_float(tf32_(g1)));
                *reinterpret_cast<float2*>(gbuf + (co + 8) * GXS + p) =
                    make_float2(__uint_as_float(tf32_(g2)), __uint_as_float(tf32_(g3)));
            }
        }
        __syncthreads();

        // ---- skip via MMA: D[256cs][128p] = Wsk[256][64] x g[64][128] ----
        {
            const float* wsk = w_skip + (size_t)l * CS_ * GC_;
            const float* bsk = b_skip + l * CS_;
            float ds[2][8][4];
            #pragma unroll
            for (int nh = 0; nh < 2; ++nh)
                #pragma unroll
                for (int nb = 0; nb < 8; ++nb)
                    #pragma unroll
                    for (int e = 0; e < 4; ++e) ds[nh][nb][e] = 0.0f;

            for (int gch = 0; gch < 4; ++gch) {   // kk chunks of 16
                const int gcb = gch * 16;
                if (gch) __syncthreads();          // prior wst readers done
                for (int idx = tid; idx < 4096; idx += NT) {
                    int gc = idx & 15; int cs = idx >> 4;
                    wst[gc * 260 + cs] = __uint_as_float(tf32_(wsk[cs * GC_ + gcb + gc]));
                }
                __syncthreads();
                #pragma unroll
                for (int s = 0; s < 2; ++s) {
                    const int kk0 = 8 * s;
                    uint32_t a0 = __float_as_uint(wst[(kk0 + tig) * 260 + m0s + gid]);
                    uint32_t a1 = __float_as_uint(wst[(kk0 + tig) * 260 + m0s + gid + 8]);
                    uint32_t a2 = __float_as_uint(wst[(kk0 + tig + 4) * 260 + m0s + gid]);
                    uint32_t a3 = __float_as_uint(wst[(kk0 + tig + 4) * 260 + m0s + gid + 8]);
                    const float* gr0 = gbuf + (gcb + kk0 + tig) * GXS + gid;
                    const float* gr1 = gr0 + 4 * GXS;
                    #pragma unroll
                    for (int nh = 0; nh < 2; ++nh) {
                        #pragma unroll
                        for (int nb = 0; nb < 8; ++nb) {
                            int pc = 64 * nh + 8 * nb;
                            uint32_t b0 = __float_as_uint(gr0[pc]);
                            uint32_t b1 = __float_as_uint(gr1[pc]);
                            mma_tf32(ds[nh][nb], a0, a1, a2, a3, b0, b1);
                        }
                    }
                }
            }
            float bs0 = __ldg(bsk + m0s + gid);
            float bs1 = __ldg(bsk + m0s + gid + 8);
            #pragma unroll
            for (int nh = 0; nh < 2; ++nh)
                #pragma unroll
                for (int nb = 0; nb < 8; ++nb) {
                    int p = 64 * nh + 8 * nb + 2 * tig;
                    if (p >= 24) {
                        int j = p - 24;
                        u64* sp0 = reinterpret_cast<u64*>(skipS + (m0s + gid) * SKS + j);
                        u64* sp1 = reinterpret_cast<u64*>(skipS + (m0s + gid + 8) * SKS + j);
                        *sp0 = add2(*sp0, pk2(ds[nh][nb][0] + bs0, ds[nh][nb][1] + bs0));
                        *sp1 = add2(*sp1, pk2(ds[nh][nb][2] + bs1, ds[nh][nb][3] + bs1));
                    }
                }
        }
        __syncthreads();

        // ---- residual via MMA: x += Wres[128][64] x g[64][128] (+b) ----
        {
            const float* wrp = w_res + (size_t)l * CR_ * GC_;
            const float* br  = b_res + l * CR_;
            float dr[8][4];
            #pragma unroll
            for (int nb = 0; nb < 8; ++nb)
                #pragma unroll
                for (int e = 0; e < 4; ++e) dr[nb][e] = 0.0f;

            for (int gch = 0; gch < 2; ++gch) {   // kk chunks of 32
                const int gcb = gch * 32;
                if (gch) __syncthreads();
                for (int idx = tid; idx < 4096; idx += NT) {
                    int gc = idx & 31; int co = idx >> 5;
                    wst[gc * 132 + co] = __uint_as_float(tf32_(wrp[co * GC_ + gcb + gc]));
                }
                __syncthreads();
                #pragma unroll
                for (int s = 0; s < 4; ++s) {
                    const int kk0 = 8 * s;
                    uint32_t a0 = __float_as_uint(wst[(kk0 + tig) * 132 + m0 + gid]);
                    uint32_t a1 = __float_as_uint(wst[(kk0 + tig) * 132 + m0 + gid + 8]);
                    uint32_t a2 = __float_as_uint(wst[(kk0 + tig + 4) * 132 + m0 + gid]);
                    uint32_t a3 = __float_as_uint(wst[(kk0 + tig + 4) * 132 + m0 + gid + 8]);
                    const float* gr0 = gbuf + (gcb + kk0 + tig) * GXS + n0 + gid;
                    const float* gr1 = gr0 + 4 * GXS;
                    #pragma unroll
                    for (int nb = 0; nb < 8; ++nb) {
                        uint32_t b0 = __float_as_uint(gr0[8 * nb]);
                        uint32_t b1 = __float_as_uint(gr1[8 * nb]);
                        mma_tf32(dr[nb], a0, a1, a2, a3, b0, b1);
                    }
                }
            }
            float br0 = __ldg(br + m0 + gid);
            float br1 = __ldg(br + m0 + gid + 8);
            #pragma unroll
            for (int nb = 0; nb < 8; ++nb) {
                int p = n0 + 8 * nb + 2 * tig;
                u64* x0 = reinterpret_cast<u64*>(bufA + (m0 + gid) * XSA + XOFF + p);
                u64* x1 = reinterpret_cast<u64*>(bufA + (m0 + gid + 8) * XSA + XOFF + p);
                u64 v0 = add2(*x0, pk2(dr[nb][0] + br0, dr[nb][1] + br0));
                u64 v1 = add2(*x1, pk2(dr[nb][2] + br1, dr[nb][3] + br1));
                if (p < pzero) { v0 = 0ULL; v1 = 0ULL; }
                *x0 = v0; *x1 = v1;
            }
        }
        __syncthreads();
    }

    // ======================= output head (proven layout) =======================
    for (int i = tid; i < N_SKIP; i += NT) {
        float v = skipS[i] * (1.0f / 12.0f);
        skipS[i] = v > 0.0f ? v : 0.0f;
    }

    float* o1buf = bufA;
    const int c0h = tid >> 1;
    const int jh  = 26 * (tid & 1);

    for (int half = 0; half < 2; ++half) {
        const int jbase = half * 52;
        // ---- out1 ----
        u64 a2p[13];
        #pragma unroll
        for (int kk = 0; kk < 13; ++kk) a2p[kk] = 0ULL;
        for (int kch = 0; kch < 16; ++kch) {
            const int kb = kch * 16;
            __syncthreads();
            for (int idx = tid; idx < 4096; idx += NT) {
                int k = idx & 15; int c = idx >> 4;
                wst[k * 260 + c] = w_out1[c * CS_ + kb + k];
            }
            __syncthreads();
            #pragma unroll 4
            for (int k = 0; k < 16; ++k) {
                u64 wb = bc2(wst[k * 260 + c0h]);
                const u64* sr = reinterpret_cast<const u64*>(skipS + (kb + k) * SKS + jbase + jh);
                #pragma unroll
                for (int kk = 0; kk < 13; ++kk) fma2(a2p[kk], wb, sr[kk]);
            }
        }
        __syncthreads();
        {
            float bi = __ldg(b_out1 + c0h);
            float* op = o1buf + c0h * O1S + jh;
            #pragma unroll
            for (int kk = 0; kk < 13; ++kk) {
                float2 v = up2(a2p[kk]);
                float v0 = v.x + bi; v0 = v0 > 0.0f ? v0 : 0.0f;
                float v1 = v.y + bi; v1 = v1 > 0.0f ? v1 : 0.0f;
                *reinterpret_cast<u64*>(op + 2 * kk) = pk2(v0, v1);
            }
        }
        __syncthreads();
        // ---- out2 ----
        u64 a3p[13];
        #pragma unroll
        for (int kk = 0; kk < 13; ++kk) a3p[kk] = 0ULL;
        for (int kch = 0; kch < 16; ++kch) {
            const int kb = kch * 16;
            __syncthreads();
            for (int idx = tid; idx < 4096; idx += NT) {
                int k = idx & 15; int c = idx >> 4;
                wst[k * 260 + c] = w_out2[c * CS_ + kb + k];
            }
            __syncthreads();
            #pragma unroll 4
            for (int k = 0; k < 16; ++k) {
                u64 wb = bc2(wst[k * 260 + c0h]);
                const u64* orr = reinterpret_cast<const u64*>(o1buf + (kb + k) * O1S + jh);
                #pragma unroll
                for (int kk = 0; kk < 13; ++kk) fma2(a3p[kk], wb, orr[kk]);
            }
        }
        {
            float bo = __ldg(b_out2 + c0h);
            float* orow = out + ((size_t)bb * V_ + c0h) * T_;
            #pragma unroll
            for (int kk = 0; kk < 13; ++kk) {
                int t = t0 + jbase + jh + 2 * kk;
                float2 v = up2(a3p[kk]);
                v.x += bo; v.y += bo;
                if (t + 1 < T_) {
                    *reinterpret_cast<float2*>(orow + t) = v;
                } else if (t < T_) {
                    orow[t] = v.x;
                }
            }
        }
        __syncthreads();
    }
}

extern "C" void kernel_launch(void* const* d_in, const int* in_sizes, int n_in,
                              void* d_out, int out_size) {
    const int*   tokens = (const int*)  d_in[0];
    const float* emb    = (const float*)d_in[1];
    const float* w_init = (const float*)d_in[2];
    const float* b_init = (const float*)d_in[3];
    const float* w_dil  = (const float*)d_in[4];
    const float* b_dil  = (const float*)d_in[5];
    const float* w_res  = (const float*)d_in[6];
    const float* b_res  = (const float*)d_in[7];
    const float* w_skip = (const float*)d_in[8];
    const float* b_skip = (const float*)d_in[9];
    const float* w_out1 = (const float*)d_in[10];
    const float* b_out1 = (const float*)d_in[11];
    const float* w_out2 = (const float*)d_in[12];
    const float* b_out2 = (const float*)d_in[13];
    float* out = (float*)d_out;

    cudaFuncSetAttribute(wavenet_fused, cudaFuncAttributeMaxDynamicSharedMemorySize, SMEM_BYTES);
    dim3 grid((T_ + TT - 1) / TT, B_);
    wavenet_fused<<<grid, NT, SMEM_BYTES>>>(
        tokens, emb, w_init, b_init, w_dil, b_dil, w_res, b_res,
        w_skip, b_skip, w_out1, b_out1, w_out2, b_out2, out);
}

// round 17
// speedup vs baseline: 3.8330x; 1.3339x over previous
#include <cuda_runtime.h>
#include <cuda_bf16.h>
#include <math.h>
#include <stdint.h>

// Problem constants
#define B_   16
#define T_   8192
#define V_   256
#define CE_  256
#define CR_  128
#define CS_  256
#define GC_  64
#define L_   12

// Tiling
#define TT   104
#define WP   128
#define GXS  136     // gbuf row stride (conflict-free MMA B loads)
#define XSA  136     // bufA row stride
#define XOFF 2       // left pad: slot (XOFF+q) holds x[q]; slots 0,1 = x[-2],x[-1]=0
#define SKS  104     // skip row stride (=13 MMA n-blocks; 104%32=8 -> conflict-free)
#define NT   512

// smem layout (floats)
#define OFF_BUFA 0
#define N_BUFA   (128*XSA)            // 17408
#define OFF_GBUF (OFF_BUFA + N_BUFA)
#define N_GBUF   (64*GXS)             // 8704; conv tf32-weight staging overlay
#define OFF_SKIP (OFF_GBUF + N_GBUF)
#define N_SKIP   (CS_*SKS)            // 26624
#define OFF_WST  (OFF_SKIP + N_SKIP)
#define N_WST    4224
#define OFF_TOK  (OFF_WST + N_WST)
#define SMEM_BYTES ((OFF_TOK)*4 + 132*4)

typedef unsigned long long u64;

__device__ __forceinline__ u64 pk2(float lo, float hi) {
    u64 r; asm("mov.b64 %0, {%1,%2};" : "=l"(r) : "f"(lo), "f"(hi)); return r;
}
__device__ __forceinline__ u64 bc2(float x) { return pk2(x, x); }
__device__ __forceinline__ void fma2(u64& d, u64 a, u64 b) {
    asm("fma.rn.f32x2 %0, %1, %2, %0;" : "+l"(d) : "l"(a), "l"(b));
}
__device__ __forceinline__ u64 add2(u64 a, u64 b) {
    u64 r; asm("add.rn.f32x2 %0, %1, %2;" : "=l"(r) : "l"(a), "l"(b)); return r;
}
__device__ __forceinline__ float2 up2(u64 a) {
    float2 f; asm("mov.b64 {%0,%1}, %2;" : "=f"(f.x), "=f"(f.y) : "l"(a)); return f;
}
__device__ __forceinline__ float sigmoidf_(float x) {
    return __fdividef(1.0f, 1.0f + __expf(-x));
}
__device__ __forceinline__ float tanhf_(float x) {
    return 1.0f - __fdividef(2.0f, __expf(2.0f * x) + 1.0f);
}
__device__ __forceinline__ uint32_t tf32_(float f) {
    uint32_t u; asm("cvt.rna.tf32.f32 %0, %1;" : "=r"(u) : "f"(f)); return u;
}
__device__ __forceinline__ void mma_tf32(float* d,
    uint32_t a0, uint32_t a1, uint32_t a2, uint32_t a3, uint32_t b0, uint32_t b1) {
    asm volatile(
        "mma.sync.aligned.m16n8k8.row.col.f32.tf32.tf32.f32 "
        "{%0,%1,%2,%3},{%4,%5,%6,%7},{%8,%9},{%0,%1,%2,%3};"
        : "+f"(d[0]), "+f"(d[1]), "+f"(d[2]), "+f"(d[3])
        : "r"(a0), "r"(a1), "r"(a2), "r"(a3), "r"(b0), "r"(b1));
}

__global__ void __launch_bounds__(NT, 1) wavenet_fused(
    const int*   __restrict__ tokens,
    const float* __restrict__ emb,
    const float* __restrict__ w_init, const float* __restrict__ b_init,
    const float* __restrict__ w_dil,  const float* __restrict__ b_dil,
    const float* __restrict__ w_res,  const float* __restrict__ b_res,
    const float* __restrict__ w_skip, const float* __restrict__ b_skip,
    const float* __restrict__ w_out1, const float* __restrict__ b_out1,
    const float* __restrict__ w_out2, const float* __restrict__ b_out2,
    float* __restrict__ out)
{
    extern __shared__ float sm[];
    float* bufA  = sm + OFF_BUFA;   // x activations [128][XSA], x[q] at col XOFF+q
    float* gbuf  = sm + OFF_GBUF;   // gate output (tf32 bits) [64][GXS]; conv weight overlay
    float* skipS = sm + OFF_SKIP;   // skip accum [256][SKS]; later s / o1 (tf32 bits)
    float* wst   = sm + OFF_WST;    // small weight staging
    int*   tokb  = (int*)(sm + OFF_TOK);

    const int tid  = threadIdx.x;
    const int tile = blockIdx.x;
    const int bb   = blockIdx.y;
    const int t0   = tile * TT;
    const int pzero = (tile == 0) ? 24 : 0;

    for (int q = tid; q < WP + 1; q += NT) {
        int t = t0 - 25 + q;
        tokb[q] = (t >= 0 && t < T_) ? tokens[bb * T_ + t] : -1;
    }
    for (int i = tid; i < N_SKIP; i += NT) skipS[i] = 0.0f;
    for (int r = tid; r < 128; r += NT) {
        bufA[r * XSA]     = 0.0f;
        bufA[r * XSA + 1] = 0.0f;
    }

    // scalar mapping (init conv only)
    const int cg = tid >> 4;
    const int pg = tid & 15;
    const int c0 = 2 * cg;
    const int q0 = 2 * pg;

    // MMA mapping
    const int warp = tid >> 5;           // 0..15
    const int lane = tid & 31;
    const int gid  = lane >> 2;          // 0..7
    const int tig  = lane & 3;           // 0..3
    const int m0   = (warp >> 1) << 4;   // conv/res: co block of 16
    const int n0   = (warp & 1) << 6;    // conv/res: p half of 64
    const int m0s  = warp << 4;          // skip/head: channel block of 16

    // ======================= init conv (emb -> x0) =======================
    {
        u64 acc[4][4];
        #pragma unroll
        for (int ic = 0; ic < 4; ++ic)
            #pragma unroll
            for (int k = 0; k < 4; ++k) acc[ic][k] = 0ULL;

        __syncthreads();
        for (int ch = 0; ch < 16; ++ch) {       // ce chunks of 16
            const int ceb = ch * 16;
            for (int idx = tid; idx < (WP + 1) * 4; idx += NT) {
                int q = idx >> 2; int ce4 = (idx & 3) << 2;
                int tok = tokb[q];
                float4 v = make_float4(0.f, 0.f, 0.f, 0.f);
                if (tok >= 0) v = *reinterpret_cast<const float4*>(emb + tok * CE_ + ceb + ce4);
                gbuf[(ce4 + 0) * GXS + q] = v.x;
                gbuf[(ce4 + 1) * GXS + q] = v.y;
                gbuf[(ce4 + 2) * GXS + q] = v.z;
                gbuf[(ce4 + 3) * GXS + q] = v.w;
            }
            for (int idx = tid; idx < 2048; idx += NT) {
                int ce = idx & 15; int co = idx >> 4;
                float2 w2 = *reinterpret_cast<const float2*>(w_init + ((co * CE_ + ceb + ce) << 1));
                wst[ce * 260 + co]       = w2.x;
                wst[ce * 260 + 128 + co] = w2.y;
            }
            __syncthreads();
            #pragma unroll
            for (int ce = 0; ce < 16; ++ce) {
                const float* hr = gbuf + ce * GXS;
                const float* wr = wst + ce * 260;
                u64 w00 = bc2(wr[c0]),        w10 = bc2(wr[128 + c0]);
                u64 w01 = bc2(wr[c0 + 1]),    w11 = bc2(wr[128 + c0 + 1]);
                u64 w02 = bc2(wr[c0 + 64]),   w12 = bc2(wr[128 + c0 + 64]);
                u64 w03 = bc2(wr[c0 + 65]),   w13 = bc2(wr[128 + c0 + 65]);
                #pragma unroll
                for (int k = 0; k < 4; ++k) {
                    int q = q0 + 32 * k;
                    u64 A = *reinterpret_cast<const u64*>(hr + q);
                    float s = hr[q + 2];
                    float2 av = up2(A);
                    u64 T1 = pk2(av.y, s);
                    fma2(acc[0][k], w00, A); fma2(acc[0][k], w10, T1);
                    fma2(acc[1][k], w01, A); fma2(acc[1][k], w11, T1);
                    fma2(acc[2][k], w02, A); fma2(acc[2][k], w12, T1);
                    fma2(acc[3][k], w03, A); fma2(acc[3][k], w13, T1);
                }
            }
            __syncthreads();
        }
        #pragma unroll
        for (int ic = 0; ic < 4; ++ic) {
            int co = (ic < 2) ? (c0 + ic) : (c0 + 62 + ic);
            u64 bp = bc2(__ldg(b_init + co));
            #pragma unroll
            for (int k = 0; k < 4; ++k) {
                int q = q0 + 32 * k;
                u64 v = (q < pzero) ? 0ULL : add2(acc[ic][k], bp);
                *reinterpret_cast<u64*>(bufA + co * XSA + XOFF + q) = v;
            }
        }
    }
    __syncthreads();

    float* wstD = gbuf;   // conv tf32 weight staging overlays gbuf

    // ============================ layers ============================
    for (int l = 0; l < L_; ++l) {
        // ---- dilated conv via tensor MMA ----
        float d[8][4];
        #pragma unroll
        for (int nb = 0; nb < 8; ++nb)
            #pragma unroll
            for (int e = 0; e < 4; ++e) d[nb][e] = 0.0f;

        const float* wd = w_dil + (size_t)l * CR_ * CR_ * 2;
        for (int ch = 0; ch < 4; ++ch) {
            const int cib = ch * 32;
            __syncthreads();
            for (int idx = tid; idx < 4096; idx += NT) {
                int ci = idx & 31; int co = idx >> 5;
                float2 w2 = *reinterpret_cast<const float2*>(wd + ((co * CR_ + cib + ci) << 1));
                wstD[ci * GXS + co]        = __uint_as_float(tf32_(w2.x));
                wstD[(32 + ci) * GXS + co] = __uint_as_float(tf32_(w2.y));
            }
            __syncthreads();
            #pragma unroll
            for (int s = 0; s < 8; ++s) {
                const int kk0 = 8 * s;
                uint32_t a0 = __float_as_uint(wstD[(kk0 + tig) * GXS + m0 + gid]);
                uint32_t a1 = __float_as_uint(wstD[(kk0 + tig) * GXS + m0 + gid + 8]);
                uint32_t a2 = __float_as_uint(wstD[(kk0 + tig + 4) * GXS + m0 + gid]);
                uint32_t a3 = __float_as_uint(wstD[(kk0 + tig + 4) * GXS + m0 + gid + 8]);
                const int ciA = cib + ((s < 4) ? (kk0 + tig) : (kk0 - 32 + tig));
                const int tp  = (s < 4) ? 0 : 2;
                const float* xr0 = bufA + ciA * XSA + tp + n0 + gid;
                const float* xr1 = xr0 + 4 * XSA;
                #pragma unroll
                for (int nb = 0; nb < 8; ++nb) {
                    uint32_t b0 = tf32_(xr0[8 * nb]);
                    uint32_t b1 = tf32_(xr1[8 * nb]);
                    mma_tf32(d[nb], a0, a1, a2, a3, b0, b1);
                }
            }
        }
        __syncthreads();

        // ---- gate ----
        const float* bd = b_dil + l * CR_;
        if (warp >= 8) {
            int coU = m0 + gid;
            float bH  = __ldg(bd + coU);
            float bH2 = __ldg(bd + coU + 8);
            #pragma unroll
            for (int nb = 0; nb < 8; ++nb) {
                int p = n0 + 8 * nb + 2 * tig;
                *reinterpret_cast<float2*>(gbuf + (coU - 64) * GXS + p) =
                    make_float2(d[nb][0] + bH, d[nb][1] + bH);
                *reinterpret_cast<float2*>(gbuf + (coU - 64 + 8) * GXS + p) =
                    make_float2(d[nb][2] + bH2, d[nb][3] + bH2);
            }
        }
        __syncthreads();
        if (warp < 8) {
            int co = m0 + gid;
            float bL  = __ldg(bd + co);
            float bL2 = __ldg(bd + co + 8);
            #pragma unroll
            for (int nb = 0; nb < 8; ++nb) {
                int p = n0 + 8 * nb + 2 * tig;
                float2 u1 = *reinterpret_cast<const float2*>(gbuf + co * GXS + p);
                float2 u2 = *reinterpret_cast<const float2*>(gbuf + (co + 8) * GXS + p);
                float g0 = tanhf_(d[nb][0] + bL)  * sigmoidf_(u1.x);
                float g1 = tanhf_(d[nb][1] + bL)  * sigmoidf_(u1.y);
                float g2 = tanhf_(d[nb][2] + bL2) * sigmoidf_(u2.x);
                float g3 = tanhf_(d[nb][3] + bL2) * sigmoidf_(u2.y);
                *reinterpret_cast<float2*>(gbuf + co * GXS + p) =
                    make_float2(__uint_as_float(tf32_(g0)), __uint_as_float(tf32_(g1)));
                *reinterpret_cast<float2*>(gbuf + (co + 8) * GXS + p) =
                    make_float2(__uint_as_float(tf32_(g2)), __uint_as_float(tf32_(g3)));
            }
        }
        __syncthreads();

        // ---- skip via MMA ----
        {
            const float* wsk = w_skip + (size_t)l * CS_ * GC_;
            const float* bsk = b_skip + l * CS_;
            float ds[2][8][4];
            #pragma unroll
            for (int nh = 0; nh < 2; ++nh)
                #pragma unroll
                for (int nb = 0; nb < 8; ++nb)
                    #pragma unroll
                    for (int e = 0; e < 4; ++e) ds[nh][nb][e] = 0.0f;

            for (int gch = 0; gch < 4; ++gch) {
                const int gcb = gch * 16;
                if (gch) __syncthreads();
                for (int idx = tid; idx < 4096; idx += NT) {
                    int gc = idx & 15; int cs = idx >> 4;
                    wst[gc * 260 + cs] = __uint_as_float(tf32_(wsk[cs * GC_ + gcb + gc]));
                }
                __syncthreads();
                #pragma unroll
                for (int s = 0; s < 2; ++s) {
                    const int kk0 = 8 * s;
                    uint32_t a0 = __float_as_uint(wst[(kk0 + tig) * 260 + m0s + gid]);
                    uint32_t a1 = __float_as_uint(wst[(kk0 + tig) * 260 + m0s + gid + 8]);
                    uint32_t a2 = __float_as_uint(wst[(kk0 + tig + 4) * 260 + m0s + gid]);
                    uint32_t a3 = __float_as_uint(wst[(kk0 + tig + 4) * 260 + m0s + gid + 8]);
                    const float* gr0 = gbuf + (gcb + kk0 + tig) * GXS + gid;
                    const float* gr1 = gr0 + 4 * GXS;
                    #pragma unroll
                    for (int nh = 0; nh < 2; ++nh) {
                        #pragma unroll
                        for (int nb = 0; nb < 8; ++nb) {
                            int pc = 64 * nh + 8 * nb;
                            uint32_t b0 = __float_as_uint(gr0[pc]);
                            uint32_t b1 = __float_as_uint(gr1[pc]);
                            mma_tf32(ds[nh][nb], a0, a1, a2, a3, b0, b1);
                        }
                    }
                }
            }
            float bs0 = __ldg(bsk + m0s + gid);
            float bs1 = __ldg(bsk + m0s + gid + 8);
            #pragma unroll
            for (int nh = 0; nh < 2; ++nh)
                #pragma unroll
                for (int nb = 0; nb < 8; ++nb) {
                    int p = 64 * nh + 8 * nb + 2 * tig;
                    if (p >= 24) {
                        int j = p - 24;
                        u64* sp0 = reinterpret_cast<u64*>(skipS + (m0s + gid) * SKS + j);
                        u64* sp1 = reinterpret_cast<u64*>(skipS + (m0s + gid + 8) * SKS + j);
                        *sp0 = add2(*sp0, pk2(ds[nh][nb][0] + bs0, ds[nh][nb][1] + bs0));
                        *sp1 = add2(*sp1, pk2(ds[nh][nb][2] + bs1, ds[nh][nb][3] + bs1));
                    }
                }
        }
        __syncthreads();

        // ---- residual via MMA ----
        {
            const float* wrp = w_res + (size_t)l * CR_ * GC_;
            const float* br  = b_res + l * CR_;
            float dr[8][4];
            #pragma unroll
            for (int nb = 0; nb < 8; ++nb)
                #pragma unroll
                for (int e = 0; e < 4; ++e) dr[nb][e] = 0.0f;

            for (int gch = 0; gch < 2; ++gch) {
                const int gcb = gch * 32;
                if (gch) __syncthreads();
                for (int idx = tid; idx < 4096; idx += NT) {
                    int gc = idx & 31; int co = idx >> 5;
                    wst[gc * 132 + co] = __uint_as_float(tf32_(wrp[co * GC_ + gcb + gc]));
                }
                __syncthreads();
                #pragma unroll
                for (int s = 0; s < 4; ++s) {
                    const int kk0 = 8 * s;
                    uint32_t a0 = __float_as_uint(wst[(kk0 + tig) * 132 + m0 + gid]);
                    uint32_t a1 = __float_as_uint(wst[(kk0 + tig) * 132 + m0 + gid + 8]);
                    uint32_t a2 = __float_as_uint(wst[(kk0 + tig + 4) * 132 + m0 + gid]);
                    uint32_t a3 = __float_as_uint(wst[(kk0 + tig + 4) * 132 + m0 + gid + 8]);
                    const float* gr0 = gbuf + (gcb + kk0 + tig) * GXS + n0 + gid;
                    const float* gr1 = gr0 + 4 * GXS;
                    #pragma unroll
                    for (int nb = 0; nb < 8; ++nb) {
                        uint32_t b0 = __float_as_uint(gr0[8 * nb]);
                        uint32_t b1 = __float_as_uint(gr1[8 * nb]);
                        mma_tf32(dr[nb], a0, a1, a2, a3, b0, b1);
                    }
                }
            }
            float br0 = __ldg(br + m0 + gid);
            float br1 = __ldg(br + m0 + gid + 8);
            #pragma unroll
            for (int nb = 0; nb < 8; ++nb) {
                int p = n0 + 8 * nb + 2 * tig;
                u64* x0 = reinterpret_cast<u64*>(bufA + (m0 + gid) * XSA + XOFF + p);
                u64* x1 = reinterpret_cast<u64*>(bufA + (m0 + gid + 8) * XSA + XOFF + p);
                u64 v0 = add2(*x0, pk2(dr[nb][0] + br0, dr[nb][1] + br0));
                u64 v1 = add2(*x1, pk2(dr[nb][2] + br1, dr[nb][3] + br1));
                if (p < pzero) { v0 = 0ULL; v1 = 0ULL; }
                *x0 = v0; *x1 = v1;
            }
        }
        __syncthreads();
    }

    // ======================= output head via tensor MMA =======================
    // s = relu(skip/12), stored as tf32 bits (in place)
    for (int i = tid; i < N_SKIP; i += NT) {
        float v = skipS[i] * (1.0f / 12.0f);
        v = v > 0.0f ? v : 0.0f;
        skipS[i] = __uint_as_float(tf32_(v));
    }
    __syncthreads();

    float dh[13][4];

    // ---- out1: o1[256][104] = W1[256][256] x s[256][104] ----
    #pragma unroll
    for (int nb = 0; nb < 13; ++nb)
        #pragma unroll
        for (int e = 0; e < 4; ++e) dh[nb][e] = 0.0f;
    for (int kch = 0; kch < 16; ++kch) {
        const int kb = kch * 16;
        if (kch) __syncthreads();
        for (int idx = tid; idx < 4096; idx += NT) {
            int k = idx & 15; int c = idx >> 4;
            wst[k * 260 + c] = __uint_as_float(tf32_(w_out1[c * CS_ + kb + k]));
        }
        __syncthreads();
        #pragma unroll
        for (int s = 0; s < 2; ++s) {
            const int kk0 = 8 * s;
            uint32_t a0 = __float_as_uint(wst[(kk0 + tig) * 260 + m0s + gid]);
            uint32_t a1 = __float_as_uint(wst[(kk0 + tig) * 260 + m0s + gid + 8]);
            uint32_t a2 = __float_as_uint(wst[(kk0 + tig + 4) * 260 + m0s + gid]);
            uint32_t a3 = __float_as_uint(wst[(kk0 + tig + 4) * 260 + m0s + gid + 8]);
            const float* sr0 = skipS + (kb + kk0 + tig) * SKS + gid;
            const float* sr1 = sr0 + 4 * SKS;
            #pragma unroll
            for (int nb = 0; nb < 13; ++nb) {
                uint32_t b0 = __float_as_uint(sr0[8 * nb]);
                uint32_t b1 = __float_as_uint(sr1[8 * nb]);
                mma_tf32(dh[nb], a0, a1, a2, a3, b0, b1);
            }
        }
    }
    __syncthreads();   // all s reads done before overwrite
    {
        float b0v = __ldg(b_out1 + m0s + gid);
        float b1v = __ldg(b_out1 + m0s + gid + 8);
        #pragma unroll
        for (int nb = 0; nb < 13; ++nb) {
            int p = 8 * nb + 2 * tig;
            float v0 = dh[nb][0] + b0v; v0 = v0 > 0.f ? v0 : 0.f;
            float v1 = dh[nb][1] + b0v; v1 = v1 > 0.f ? v1 : 0.f;
            float v2 = dh[nb][2] + b1v; v2 = v2 > 0.f ? v2 : 0.f;
            float v3 = dh[nb][3] + b1v; v3 = v3 > 0.f ? v3 : 0.f;
            *reinterpret_cast<float2*>(skipS + (m0s + gid) * SKS + p) =
                make_float2(__uint_as_float(tf32_(v0)), __uint_as_float(tf32_(v1)));
            *reinterpret_cast<float2*>(skipS + (m0s + gid + 8) * SKS + p) =
                make_float2(__uint_as_float(tf32_(v2)), __uint_as_float(tf32_(v3)));
        }
    }
    __syncthreads();

    // ---- out2: out[256][104] = W2[256][256] x o1[256][104] ----
    #pragma unroll
    for (int nb = 0; nb < 13; ++nb)
        #pragma unroll
        for (int e = 0; e < 4; ++e) dh[nb][e] = 0.0f;
    for (int kch = 0; kch < 16; ++kch) {
        const int kb = kch * 16;
        if (kch) __syncthreads();
        for (int idx = tid; idx < 4096; idx += NT) {
            int k = idx & 15; int c = idx >> 4;
            wst[k * 260 + c] = __uint_as_float(tf32_(w_out2[c * CS_ + kb + k]));
        }
        __syncthreads();
        #pragma unroll
        for (int s = 0; s < 2; ++s) {
            const int kk0 = 8 * s;
            uint32_t a0 = __float_as_uint(wst[(kk0 + tig) * 260 + m0s + gid]);
            uint32_t a1 = __float_as_uint(wst[(kk0 + tig) * 260 + m0s + gid + 8]);
            uint32_t a2 = __float_as_uint(wst[(kk0 + tig + 4) * 260 + m0s + gid]);
            uint32_t a3 = __float_as_uint(wst[(kk0 + tig + 4) * 260 + m0s + gid + 8]);
            const float* sr0 = skipS + (kb + kk0 + tig) * SKS + gid;
            const float* sr1 = sr0 + 4 * SKS;
            #pragma unroll
            for (int nb = 0; nb < 13; ++nb) {
                uint32_t b0 = __float_as_uint(sr0[8 * nb]);
                uint32_t b1 = __float_as_uint(sr1[8 * nb]);
                mma_tf32(dh[nb], a0, a1, a2, a3, b0, b1);
            }
        }
    }
    {
        float bo0 = __ldg(b_out2 + m0s + gid);
        float bo1 = __ldg(b_out2 + m0s + gid + 8);
        float* orow0 = out + ((size_t)bb * V_ + m0s + gid) * T_;
        float* orow1 = out + ((size_t)bb * V_ + m0s + gid + 8) * T_;
        #pragma unroll
        for (int nb = 0; nb < 13; ++nb) {
            int p = 8 * nb + 2 * tig;
            int t = t0 + p;
            if (t + 1 < T_) {
                *reinterpret_cast<float2*>(orow0 + t) = make_float2(dh[nb][0] + bo0, dh[nb][1] + bo0);
                *reinterpret_cast<float2*>(orow1 + t) = make_float2(dh[nb][2] + bo1, dh[nb][3] + bo1);
            } else if (t < T_) {
                orow0[t] = dh[nb][0] + bo0;
                orow1[t] = dh[nb][2] + bo1;
            }
        }
    }
}

extern "C" void kernel_launch(void* const* d_in, const int* in_sizes, int n_in,
                              void* d_out, int out_size) {
    const int*   tokens = (const int*)  d_in[0];
    const float* emb    = (const float*)d_in[1];
    const float* w_init = (const float*)d_in[2];
    const float* b_init = (const float*)d_in[3];
    const float* w_dil  = (const float*)d_in[4];
    const float* b_dil  = (const float*)d_in[5];
    const float* w_res  = (const float*)d_in[6];
    const float* b_res  = (const float*)d_in[7];
    const float* w_skip = (const float*)d_in[8];
    const float* b_skip = (const float*)d_in[9];
    const float* w_out1 = (const float*)d_in[10];
    const float* b_out1 = (const float*)d_in[11];
    const float* w_out2 = (const float*)d_in[12];
    const float* b_out2 = (const float*)d_in[13];
    float* out = (float*)d_out;

    cudaFuncSetAttribute(wavenet_fused, cudaFuncAttributeMaxDynamicSharedMemorySize, SMEM_BYTES);
    dim3 grid((T_ + TT - 1) / TT, B_);
    wavenet_fused<<<grid, NT, SMEM_BYTES>>>(
        tokens, emb, w_init, b_init, w_dil, b_dil, w_res, b_res,
        w_skip, b_skip, w_out1, b_out1, w_out2, b_out2, out);
}